// round 4
// baseline (speedup 1.0000x reference)
#include <cuda_runtime.h>

// ---------------------------------------------------------------------------
// Groupwise CNN + 32 independent 2-layer LSTMs + gaussian head
// ---------------------------------------------------------------------------

typedef unsigned long long ull;

#define B_    128
#define W_    128
#define FC1_  32
#define H_    32

// scratch (allocation-free rule: __device__ globals)
__device__ float g_pool[16384 * 1040];       // [b*128+w][k*65+j]  (68MB)
__device__ float g_z[FC1_ * 16384];          // [f][b*128+t]  (transposed for lstm)
__device__ float g_comb[B_ * FC1_ * H_];     // [b][f*32+h]

__device__ __forceinline__ void ffma2(ull &d, ull a, ull b) {
    asm("fma.rn.f32x2 %0, %1, %2, %0;" : "+l"(d) : "l"(a), "l"(b));
}
__device__ __forceinline__ float redu(ull a) {
    float lo, hi;
    asm("mov.b64 {%0,%1}, %2;" : "=f"(lo), "=f"(hi) : "l"(a));
    return lo + hi;
}
__device__ __forceinline__ ull pk2(float lo, float hi) {
    ull r;
    asm("mov.b64 %0, {%1,%2};" : "=l"(r) : "f"(lo), "f"(hi));
    return r;
}
__device__ __forceinline__ float sigmf(float x) {
    return __fdividef(1.0f, 1.0f + __expf(-x));
}
__device__ __forceinline__ float tanhfa(float x) {
    return __fdividef(2.0f, 1.0f + __expf(-2.0f * x)) - 1.0f;
}

// ---------------------------------------------------------------------------
// Kernel 1a: conv -> relu -> maxpool. One block per (b,w) row; massively
// parallel, mem-light. Writes pooled rows to g_pool.
// ---------------------------------------------------------------------------
__global__ __launch_bounds__(256) void k_conv(
    const float* __restrict__ x,
    const float* __restrict__ conv_w, const float* __restrict__ conv_b)
{
    __shared__ float xr[130], cwv[48], cbv[16];
    const int tid = threadIdx.x;
    const int row = blockIdx.x;            // b*128 + w
    const int w   = row & 127;

    if (tid < 128)                    xr[tid + 1]    = x[row * 128 + tid];
    else if (tid == 128)              { xr[0] = 0.0f; xr[129] = 0.0f; }
    if (tid >= 160 && tid < 208)      cwv[tid - 160] = conv_w[w * 48 + (tid - 160)];
    if (tid >= 224 && tid < 240)      cbv[tid - 224] = conv_b[w * 16 + (tid - 224)];
    __syncthreads();

    for (int o = tid; o < 1040; o += 256) {
        int k = o / 65;
        int j = o - 65 * k;
        float c0 = cwv[k * 3], c1 = cwv[k * 3 + 1], c2 = cwv[k * 3 + 2], bb = cbv[k];
        int p = 2 * j;
        float va = -1e30f, vb = -1e30f;
        if (p > 0)
            va = fmaxf(0.0f, bb + c0 * xr[p - 1] + c1 * xr[p]     + c2 * xr[p + 1]);
        if (p < 128)
            vb = fmaxf(0.0f, bb + c0 * xr[p]     + c1 * xr[p + 1] + c2 * xr[p + 2]);
        g_pool[(size_t)row * 1040 + o] = fmaxf(va, vb);
    }
}

// ---------------------------------------------------------------------------
// Kernel 1b: fc1 GEMM. z[f][row] = dot(pooled[row][:], W[f][:]) + bias[f].
// Block = 128 rows (8 tiles of 16). W (133KB) + tile (65KB) in smem.
// Warp = (K-chunk c of 4, row-group g of 2): lane=output, 8 rows/thread,
// weight LDS.128 lane-distinct (261-quad odd stride: conflict-free),
// pooled reads are broadcasts. 4 K-chunk partials combined via smem.
// Output written TRANSPOSED: g_z[f][b*128+t] (contiguous for k_lstm).
// ---------------------------------------------------------------------------
__global__ __launch_bounds__(256) void k_fc1(
    const float* __restrict__ fc1_w, const float* __restrict__ fc1_b)
{
    extern __shared__ float smf[];
    float* Wfp  = smf;                // 32 x 1044 = 33408
    float* sp   = Wfp + 33408;        // 16 x 1044 = 16704
    float* part = sp + 16704;         // 4c x 16r x 32o = 2048
    float* fb   = part + 2048;        // 32

    const int tid = threadIdx.x;

    for (int o = 0; o < 32; ++o)
        for (int c = tid; c < 1040; c += 256)
            Wfp[o * 1044 + c] = fc1_w[o * 1040 + c];
    if (tid < 32) fb[tid] = fc1_b[tid];

    const int wid = tid >> 5, lane = tid & 31;
    const int cch = wid >> 1;          // K-chunk 0..3 (65 quads)
    const int g   = wid & 1;           // row-group 0..1 (8 rows)
    const int qb  = cch * 65;
    const int row_base = blockIdx.x * 128;

    for (int tile = 0; tile < 8; ++tile) {
        const int row0 = row_base + tile * 16;
        __syncthreads();
        // load 16 pooled rows (float4, coalesced)
        for (int idx = tid; idx < 4160; idx += 256) {
            int rr = idx / 260;
            int q  = idx - rr * 260;
            ((float4*)(sp + rr * 1044))[q] =
                ((const float4*)g_pool)[(size_t)(row0 + rr) * 260 + q];
        }
        __syncthreads();

        // GEMM over K-chunk
        {
            const ulonglong2* wrow = (const ulonglong2*)(Wfp + lane * 1044) + qb;
            ull acc[8] = {0, 0, 0, 0, 0, 0, 0, 0};
            #pragma unroll 5
            for (int q = 0; q < 65; ++q) {
                ulonglong2 wv = wrow[q];
                #pragma unroll
                for (int r = 0; r < 8; ++r) {
                    ulonglong2 hv = ((const ulonglong2*)(sp + (g * 8 + r) * 1044))[qb + q];
                    ffma2(acc[r], hv.x, wv.x);
                    ffma2(acc[r], hv.y, wv.y);
                }
            }
            #pragma unroll
            for (int r = 0; r < 8; ++r)
                part[(cch * 16 + g * 8 + r) * 32 + lane] = redu(acc[r]);
        }
        __syncthreads();

        // combine partials + bias; transposed store
        for (int idx = tid; idx < 512; idx += 256) {
            int rr = idx >> 5, o = idx & 31;
            float s = fb[o]
                    + part[(0 * 16 + rr) * 32 + o]
                    + part[(1 * 16 + rr) * 32 + o]
                    + part[(2 * 16 + rr) * 32 + o]
                    + part[(3 * 16 + rr) * 32 + o];
            g_z[o * 16384 + row0 + rr] = s;
        }
    }
}

// ---------------------------------------------------------------------------
// Kernel 2: the LSTM. Block = (f, 32-batch chunk), 128 threads (4 warps).
// warp <-> 8 cells; lane = hidden index (owns gates lane,+32,+64,+96).
// 8 cells/warp amortizes weight LDS: crossbar 2304 cyc/SM/step < FMA 3072.
// Warps fully independent across the 128-step loop (no __syncthreads).
// ---------------------------------------------------------------------------
__global__ __launch_bounds__(128, 1) void k_lstm(
    const float* __restrict__ w_ih0, const float* __restrict__ w_ih1,
    const float* __restrict__ w_hh,  const float* __restrict__ b_lstm)
{
    extern __shared__ ull sm2[];
    ulonglong2* W0q = (ulonglong2*)sm2;            // [8 hp2][128 g]   16KB
    ulonglong2* Wcq = (ulonglong2*)(sm2 + 2048);   // [16 hp2][128 g]  32KB
    ull*   hcat = sm2 + 6144;                      // [32 cells][32 pairs] 8KB
    float* zb   = (float*)(sm2 + 7168);            // [32 b][128 t]    16KB
    float* wi0  = zb + 4096;                       // 128
    float* bs0  = wi0 + 128;                       // 128
    float* bs1  = bs0 + 128;                       // 128

    const int tid = threadIdx.x;
    const int f   = blockIdx.x & 31;
    const int b0  = (blockIdx.x >> 5) * 32;

    const float* whh0 = w_hh  + (size_t)f        * 4096;  // [g][h]
    const float* whh1 = w_hh  + (size_t)(32 + f) * 4096;
    const float* wi1  = w_ih1 + (size_t)f        * 4096;

    for (int idx = tid; idx < 1024; idx += 128) {
        int hp2 = idx >> 7, gg = idx & 127;
        float4 v = *(const float4*)(whh0 + gg * 32 + 4 * hp2);
        W0q[idx] = make_ulonglong2(pk2(v.x, v.y), pk2(v.z, v.w));
    }
    for (int idx = tid; idx < 2048; idx += 128) {
        int hp2 = idx >> 7, gg = idx & 127;
        float4 v = (hp2 < 8) ? *(const float4*)(wi1  + gg * 32 + 4 * hp2)
                             : *(const float4*)(whh1 + gg * 32 + 4 * (hp2 - 8));
        Wcq[idx] = make_ulonglong2(pk2(v.x, v.y), pk2(v.z, v.w));
    }
    if (tid < 128) {
        wi0[tid] = w_ih0[f * 128 + tid];
        bs0[tid] = b_lstm[f * 128 + tid];
        bs1[tid] = b_lstm[(32 + f) * 128 + tid];
    }
    // z for this (f, b-chunk): contiguous 16KB copy
    for (int idx = tid; idx < 4096; idx += 128)
        zb[idx] = g_z[f * 16384 + b0 * 128 + idx];
    for (int idx = tid; idx < 1024; idx += 128) hcat[idx] = 0ull;
    __syncthreads();

    const int wg = tid >> 5, lane = tid & 31;
    ull* hbase = hcat + (wg * 8) * 32;             // 8 cells x 32 pairs

    // per-lane hoisted scalars
    float wi0g[4], bs0g[4], bs1g[4];
    #pragma unroll
    for (int gg = 0; gg < 4; ++gg) {
        wi0g[gg] = wi0[lane + 32 * gg];
        bs0g[gg] = bs0[lane + 32 * gg];
        bs1g[gg] = bs1[lane + 32 * gg];
    }

    float c0[8] = {0, 0, 0, 0, 0, 0, 0, 0};
    float c1[8] = {0, 0, 0, 0, 0, 0, 0, 0};
    const float* zw = zb + (wg * 8) * 128;

    for (int t = 0; t < 128; ++t) {
        // ---- layer 0: gates = x*wi0 + b0 + h0_prev @ whh0 ----
        ull a[8][4];
        #pragma unroll
        for (int r = 0; r < 8; ++r) {
            float xv = zw[r * 128 + t];
            #pragma unroll
            for (int gg = 0; gg < 4; ++gg)
                a[r][gg] = pk2(fmaf(xv, wi0g[gg], bs0g[gg]), 0.0f);
        }
        #pragma unroll
        for (int hp2 = 0; hp2 < 8; ++hp2) {
            ulonglong2 w0 = W0q[hp2 * 128 + lane];
            ulonglong2 w1 = W0q[hp2 * 128 + lane + 32];
            ulonglong2 w2 = W0q[hp2 * 128 + lane + 64];
            ulonglong2 w3 = W0q[hp2 * 128 + lane + 96];
            #pragma unroll
            for (int r = 0; r < 8; ++r) {
                ulonglong2 hv = ((const ulonglong2*)(hbase + r * 32))[hp2];
                ffma2(a[r][0], hv.x, w0.x); ffma2(a[r][0], hv.y, w0.y);
                ffma2(a[r][1], hv.x, w1.x); ffma2(a[r][1], hv.y, w1.y);
                ffma2(a[r][2], hv.x, w2.x); ffma2(a[r][2], hv.y, w2.y);
                ffma2(a[r][3], hv.x, w3.x); ffma2(a[r][3], hv.y, w3.y);
            }
        }
        #pragma unroll
        for (int r = 0; r < 8; ++r) {
            float gi  = redu(a[r][0]);
            float gf  = redu(a[r][1]);
            float gg_ = redu(a[r][2]);
            float go  = redu(a[r][3]);
            c0[r] = sigmf(gf) * c0[r] + sigmf(gi) * tanhfa(gg_);
            ((float*)(hbase + r * 32))[lane] = sigmf(go) * tanhfa(c0[r]);
        }
        __syncwarp();

        // ---- layer 1: gates = b1 + [h0_new ; h1_prev] @ [wi1 ; whh1] ----
        #pragma unroll
        for (int r = 0; r < 8; ++r) {
            #pragma unroll
            for (int gg = 0; gg < 4; ++gg)
                a[r][gg] = pk2(bs1g[gg], 0.0f);
        }
        #pragma unroll
        for (int hp2 = 0; hp2 < 16; ++hp2) {
            ulonglong2 w0 = Wcq[hp2 * 128 + lane];
            ulonglong2 w1 = Wcq[hp2 * 128 + lane + 32];
            ulonglong2 w2 = Wcq[hp2 * 128 + lane + 64];
            ulonglong2 w3 = Wcq[hp2 * 128 + lane + 96];
            #pragma unroll
            for (int r = 0; r < 8; ++r) {
                ulonglong2 hv = ((const ulonglong2*)(hbase + r * 32))[hp2];
                ffma2(a[r][0], hv.x, w0.x); ffma2(a[r][0], hv.y, w0.y);
                ffma2(a[r][1], hv.x, w1.x); ffma2(a[r][1], hv.y, w1.y);
                ffma2(a[r][2], hv.x, w2.x); ffma2(a[r][2], hv.y, w2.y);
                ffma2(a[r][3], hv.x, w3.x); ffma2(a[r][3], hv.y, w3.y);
            }
        }
        #pragma unroll
        for (int r = 0; r < 8; ++r) {
            float gi  = redu(a[r][0]);
            float gf  = redu(a[r][1]);
            float gg_ = redu(a[r][2]);
            float go  = redu(a[r][3]);
            c1[r] = sigmf(gf) * c1[r] + sigmf(gi) * tanhfa(gg_);
            ((float*)(hbase + r * 32))[32 + lane] = sigmf(go) * tanhfa(c1[r]);
        }
        __syncwarp();
    }

    #pragma unroll
    for (int r = 0; r < 8; ++r)
        g_comb[(size_t)(b0 + wg * 8 + r) * 1024 + f * 32 + lane] =
            ((float*)(hbase + r * 32))[32 + lane];
}

// ---------------------------------------------------------------------------
// Kernel 3: gaussian head. Block per b.
// ---------------------------------------------------------------------------
__global__ __launch_bounds__(128) void k_head(
    const float* __restrict__ mu_w, const float* __restrict__ mu_b,
    const float* __restrict__ lv_w, const float* __restrict__ lv_b,
    float* __restrict__ out)
{
    __shared__ float smu[4], slv[4];
    const int tid = threadIdx.x, b = blockIdx.x;
    float am = 0.0f, al = 0.0f;
    for (int i = tid; i < 1024; i += 128) {
        float v = g_comb[(size_t)b * 1024 + i];
        am += v * mu_w[i];
        al += v * lv_w[i];
    }
    #pragma unroll
    for (int s = 16; s > 0; s >>= 1) {
        am += __shfl_xor_sync(0xffffffffu, am, s);
        al += __shfl_xor_sync(0xffffffffu, al, s);
    }
    const int wg = tid >> 5, lane = tid & 31;
    if (lane == 0) { smu[wg] = am; slv[wg] = al; }
    __syncthreads();
    if (tid == 0) {
        float mu = smu[0] + smu[1] + smu[2] + smu[3] + mu_b[0];
        float lv = slv[0] + slv[1] + slv[2] + slv[3] + lv_b[0];
        float sg = expf(0.5f * lv);
        out[b]       = mu - 1.96f * sg;
        out[128 + b] = mu;
        out[256 + b] = mu + 1.96f * sg;
        out[384 + b] = lv;
    }
}

// ---------------------------------------------------------------------------
extern "C" void kernel_launch(void* const* d_in, const int* in_sizes, int n_in,
                              void* d_out, int out_size)
{
    const float* x      = (const float*)d_in[0];
    const float* conv_w = (const float*)d_in[1];
    const float* conv_b = (const float*)d_in[2];
    const float* fc1_w  = (const float*)d_in[3];
    const float* fc1_b  = (const float*)d_in[4];
    const float* w_ih0  = (const float*)d_in[5];
    const float* w_ih1  = (const float*)d_in[6];
    const float* w_hh   = (const float*)d_in[7];
    const float* b_lstm = (const float*)d_in[8];
    const float* mu_w   = (const float*)d_in[9];
    const float* mu_b   = (const float*)d_in[10];
    const float* lv_w   = (const float*)d_in[11];
    const float* lv_b   = (const float*)d_in[12];
    float* out = (float*)d_out;

    const int SM_FC1  = (33408 + 16704 + 2048 + 32) * (int)sizeof(float);  // 208,768 B
    const int SM_LSTM = 9408 * (int)sizeof(ull);                           //  75,264 B

    cudaFuncSetAttribute(k_fc1,  cudaFuncAttributeMaxDynamicSharedMemorySize, SM_FC1);
    cudaFuncSetAttribute(k_lstm, cudaFuncAttributeMaxDynamicSharedMemorySize, SM_LSTM);

    k_conv<<<16384, 256>>>(x, conv_w, conv_b);
    k_fc1<<<128, 256, SM_FC1>>>(fc1_w, fc1_b);
    k_lstm<<<128, 128, SM_LSTM>>>(w_ih0, w_ih1, w_hh, b_lstm);
    k_head<<<128, 128>>>(mu_w, mu_b, lv_w, lv_b, out);
}

// round 5
// speedup vs baseline: 1.3787x; 1.3787x over previous
#include <cuda_runtime.h>

// ---------------------------------------------------------------------------
// Groupwise CNN + 32 independent 2-layer LSTMs + gaussian head
// ---------------------------------------------------------------------------

typedef unsigned long long ull;

#define B_    128
#define W_    128
#define FC1_  32
#define H_    32

// scratch (allocation-free rule: __device__ globals)
__device__ float g_pool[16384 * 1040];       // [b*128+w][k*65+j]
__device__ float g_z[FC1_ * 16384];          // [f][b*128+t]  (transposed for lstm)
__device__ float g_comb[B_ * FC1_ * H_];     // [b][f*32+h]

__device__ __forceinline__ void ffma2(ull &d, ull a, ull b) {
    asm("fma.rn.f32x2 %0, %1, %2, %0;" : "+l"(d) : "l"(a), "l"(b));
}
__device__ __forceinline__ float redu(ull a) {
    float lo, hi;
    asm("mov.b64 {%0,%1}, %2;" : "=f"(lo), "=f"(hi) : "l"(a));
    return lo + hi;
}
__device__ __forceinline__ ull pk2(float lo, float hi) {
    ull r;
    asm("mov.b64 %0, {%1,%2};" : "=l"(r) : "f"(lo), "f"(hi));
    return r;
}
__device__ __forceinline__ float sigmf(float x) {
    return __fdividef(1.0f, 1.0f + __expf(-x));
}
__device__ __forceinline__ float tanhfa(float x) {
    return __fdividef(2.0f, 1.0f + __expf(-2.0f * x)) - 1.0f;
}

// ---------------------------------------------------------------------------
// Kernel 1a: conv -> relu -> maxpool. One block per (b,w) row.
// ---------------------------------------------------------------------------
__global__ __launch_bounds__(256) void k_conv(
    const float* __restrict__ x,
    const float* __restrict__ conv_w, const float* __restrict__ conv_b)
{
    __shared__ float xr[130], cwv[48], cbv[16];
    const int tid = threadIdx.x;
    const int row = blockIdx.x;            // b*128 + w
    const int w   = row & 127;

    if (tid < 128)                    xr[tid + 1]    = x[row * 128 + tid];
    else if (tid == 128)              { xr[0] = 0.0f; xr[129] = 0.0f; }
    if (tid >= 160 && tid < 208)      cwv[tid - 160] = conv_w[w * 48 + (tid - 160)];
    if (tid >= 224 && tid < 240)      cbv[tid - 224] = conv_b[w * 16 + (tid - 224)];
    __syncthreads();

    for (int o = tid; o < 1040; o += 256) {
        int k = o / 65;
        int j = o - 65 * k;
        float c0 = cwv[k * 3], c1 = cwv[k * 3 + 1], c2 = cwv[k * 3 + 2], bb = cbv[k];
        int p = 2 * j;
        float va = -1e30f, vb = -1e30f;
        if (p > 0)
            va = fmaxf(0.0f, bb + c0 * xr[p - 1] + c1 * xr[p]     + c2 * xr[p + 1]);
        if (p < 128)
            vb = fmaxf(0.0f, bb + c0 * xr[p]     + c1 * xr[p + 1] + c2 * xr[p + 2]);
        g_pool[(size_t)row * 1040 + o] = fmaxf(va, vb);
    }
}

// ---------------------------------------------------------------------------
// Kernel 1b: fc1 GEMM, 512 threads. Block = 128 rows (8 tiles of 16).
// Warp = (K-chunk cch of 4, row-group g of 4): lane=output, 4 rows/thread.
// Weight LDS.128 lane-distinct (odd 261-quad stride: conflict-free);
// pooled reads broadcast. Output TRANSPOSED: g_z[f][b*128+t].
// ---------------------------------------------------------------------------
__global__ __launch_bounds__(512) void k_fc1(
    const float* __restrict__ fc1_w, const float* __restrict__ fc1_b)
{
    extern __shared__ float smf[];
    float* Wfp  = smf;                // 32 x 1044 = 33408
    float* sp   = Wfp + 33408;        // 16 x 1044 = 16704
    float* part = sp + 16704;         // 4c x 16r x 32o = 2048
    float* fb   = part + 2048;        // 32

    const int tid = threadIdx.x;

    for (int o = 0; o < 32; ++o)
        for (int c = tid; c < 1040; c += 512)
            Wfp[o * 1044 + c] = fc1_w[o * 1040 + c];
    if (tid < 32) fb[tid] = fc1_b[tid];

    const int wid = tid >> 5, lane = tid & 31;
    const int cch = wid >> 2;          // K-chunk 0..3 (65 quads)
    const int g   = wid & 3;           // row-group 0..3 (4 rows)
    const int qb  = cch * 65;
    const int row_base = blockIdx.x * 128;

    for (int tile = 0; tile < 8; ++tile) {
        const int row0 = row_base + tile * 16;
        __syncthreads();
        // load 16 pooled rows (float4, coalesced)
        for (int idx = tid; idx < 4160; idx += 512) {
            int rr = idx / 260;
            int q  = idx - rr * 260;
            ((float4*)(sp + rr * 1044))[q] =
                ((const float4*)g_pool)[(size_t)(row0 + rr) * 260 + q];
        }
        __syncthreads();

        // GEMM over K-chunk: 4 rows per thread
        {
            const ulonglong2* wrow = (const ulonglong2*)(Wfp + lane * 1044) + qb;
            ull acc[4] = {0, 0, 0, 0};
            #pragma unroll 5
            for (int q = 0; q < 65; ++q) {
                ulonglong2 wv = wrow[q];
                #pragma unroll
                for (int r = 0; r < 4; ++r) {
                    ulonglong2 hv = ((const ulonglong2*)(sp + (g * 4 + r) * 1044))[qb + q];
                    ffma2(acc[r], hv.x, wv.x);
                    ffma2(acc[r], hv.y, wv.y);
                }
            }
            #pragma unroll
            for (int r = 0; r < 4; ++r)
                part[(cch * 16 + g * 4 + r) * 32 + lane] = redu(acc[r]);
        }
        __syncthreads();

        // combine partials + bias; transposed store
        {
            int rr = tid >> 5, o = tid & 31;
            float s = fb[o]
                    + part[(0 * 16 + rr) * 32 + o]
                    + part[(1 * 16 + rr) * 32 + o]
                    + part[(2 * 16 + rr) * 32 + o]
                    + part[(3 * 16 + rr) * 32 + o];
            g_z[o * 16384 + row0 + rr] = s;
        }
    }
}

// ---------------------------------------------------------------------------
// Kernel 2: the LSTM. Block = (f, 32-batch chunk), 256 threads (8 warps).
// warp <-> 4 cells; lane = hidden index (owns gates lane,+32,+64,+96).
// SOFTWARE-PIPELINED: gates1(t) and gates0(t+1) computed in ONE merged GEMM
// block (sharing h0(t) broadcast loads); activation chains A1(t) and A0(t+1)
// are adjacent independent chains across the loop back-edge (unroll 2).
// No __syncthreads in the loop; warps fully independent.
// ---------------------------------------------------------------------------
__global__ __launch_bounds__(256, 1) void k_lstm(
    const float* __restrict__ w_ih0, const float* __restrict__ w_ih1,
    const float* __restrict__ w_hh,  const float* __restrict__ b_lstm)
{
    extern __shared__ ull sm2[];
    ulonglong2* W0q = (ulonglong2*)sm2;            // [8 hp2][128 g]   16KB
    ulonglong2* Wcq = (ulonglong2*)(sm2 + 2048);   // [16 hp2][128 g]  32KB
    ull*   hcat = sm2 + 6144;                      // [32 cells][32 pairs] 8KB
    float* zb   = (float*)(sm2 + 7168);            // [32 b][128 t]    16KB
    float* wi0  = zb + 4096;                       // 128
    float* bs0  = wi0 + 128;                       // 128
    float* bs1  = bs0 + 128;                       // 128

    const int tid = threadIdx.x;
    const int f   = blockIdx.x & 31;
    const int b0  = (blockIdx.x >> 5) * 32;

    const float* whh0 = w_hh  + (size_t)f        * 4096;  // [g][h]
    const float* whh1 = w_hh  + (size_t)(32 + f) * 4096;
    const float* wi1  = w_ih1 + (size_t)f        * 4096;

    for (int idx = tid; idx < 1024; idx += 256) {
        int hp2 = idx >> 7, gg = idx & 127;
        float4 v = *(const float4*)(whh0 + gg * 32 + 4 * hp2);
        W0q[idx] = make_ulonglong2(pk2(v.x, v.y), pk2(v.z, v.w));
    }
    for (int idx = tid; idx < 2048; idx += 256) {
        int hp2 = idx >> 7, gg = idx & 127;
        float4 v = (hp2 < 8) ? *(const float4*)(wi1  + gg * 32 + 4 * hp2)
                             : *(const float4*)(whh1 + gg * 32 + 4 * (hp2 - 8));
        Wcq[idx] = make_ulonglong2(pk2(v.x, v.y), pk2(v.z, v.w));
    }
    if (tid < 128) {
        wi0[tid] = w_ih0[f * 128 + tid];
        bs0[tid] = b_lstm[f * 128 + tid];
        bs1[tid] = b_lstm[(32 + f) * 128 + tid];
    }
    for (int idx = tid; idx < 4096; idx += 256)
        zb[idx] = g_z[f * 16384 + b0 * 128 + idx];
    for (int idx = tid; idx < 1024; idx += 256) hcat[idx] = 0ull;
    __syncthreads();

    const int wg = tid >> 5, lane = tid & 31;
    ull* hbase = hcat + (wg * 4) * 32;             // 4 cells x 32 pairs

    // per-lane hoisted scalars
    float wi0g[4], bs0g[4], bs1g[4];
    #pragma unroll
    for (int gg = 0; gg < 4; ++gg) {
        wi0g[gg] = wi0[lane + 32 * gg];
        bs0g[gg] = bs0[lane + 32 * gg];
        bs1g[gg] = bs1[lane + 32 * gg];
    }

    float c0[4] = {0, 0, 0, 0};
    float c1[4] = {0, 0, 0, 0};
    float h1v[4];
    const float* zw = zb + (wg * 4) * 128;

    // prologue: gates0(t=0) = x(0)*wi0 + b0  (h0(-1)=0: no GEMM term)
    ull a0[4][4];
    #pragma unroll
    for (int r = 0; r < 4; ++r) {
        float xv = zw[r * 128];
        #pragma unroll
        for (int gg = 0; gg < 4; ++gg)
            a0[r][gg] = pk2(fmaf(xv, wi0g[gg], bs0g[gg]), 0.0f);
    }

    #pragma unroll 2
    for (int t = 0; t < 128; ++t) {
        // ---- A0: h0(t) from a0 ----
        #pragma unroll
        for (int r = 0; r < 4; ++r) {
            float gi  = redu(a0[r][0]);
            float gf  = redu(a0[r][1]);
            float gg_ = redu(a0[r][2]);
            float go  = redu(a0[r][3]);
            c0[r] = sigmf(gf) * c0[r] + sigmf(gi) * tanhfa(gg_);
            ((float*)(hbase + r * 32))[lane] = sigmf(go) * tanhfa(c0[r]);
        }
        __syncwarp();

        // ---- merged GEMM: a1 = gates1(t), a0 = gates0(t+1) ----
        ull a1[4][4];
        {
            const int tn = (t + 1) & 127;
            #pragma unroll
            for (int r = 0; r < 4; ++r) {
                float xv = zw[r * 128 + tn];
                #pragma unroll
                for (int gg = 0; gg < 4; ++gg) {
                    a1[r][gg] = pk2(bs1g[gg], 0.0f);
                    a0[r][gg] = pk2(fmaf(xv, wi0g[gg], bs0g[gg]), 0.0f);
                }
            }
        }
        // first half: contract over h0(t) — feeds BOTH layer1 and layer0-next
        #pragma unroll
        for (int hp2 = 0; hp2 < 8; ++hp2) {
            ulonglong2 u0 = Wcq[hp2 * 128 + lane];
            ulonglong2 u1 = Wcq[hp2 * 128 + lane + 32];
            ulonglong2 u2 = Wcq[hp2 * 128 + lane + 64];
            ulonglong2 u3 = Wcq[hp2 * 128 + lane + 96];
            ulonglong2 v0 = W0q[hp2 * 128 + lane];
            ulonglong2 v1 = W0q[hp2 * 128 + lane + 32];
            ulonglong2 v2 = W0q[hp2 * 128 + lane + 64];
            ulonglong2 v3 = W0q[hp2 * 128 + lane + 96];
            #pragma unroll
            for (int r = 0; r < 4; ++r) {
                ulonglong2 hv = ((const ulonglong2*)(hbase + r * 32))[hp2];
                ffma2(a1[r][0], hv.x, u0.x); ffma2(a1[r][0], hv.y, u0.y);
                ffma2(a1[r][1], hv.x, u1.x); ffma2(a1[r][1], hv.y, u1.y);
                ffma2(a1[r][2], hv.x, u2.x); ffma2(a1[r][2], hv.y, u2.y);
                ffma2(a1[r][3], hv.x, u3.x); ffma2(a1[r][3], hv.y, u3.y);
                ffma2(a0[r][0], hv.x, v0.x); ffma2(a0[r][0], hv.y, v0.y);
                ffma2(a0[r][1], hv.x, v1.x); ffma2(a0[r][1], hv.y, v1.y);
                ffma2(a0[r][2], hv.x, v2.x); ffma2(a0[r][2], hv.y, v2.y);
                ffma2(a0[r][3], hv.x, v3.x); ffma2(a0[r][3], hv.y, v3.y);
            }
        }
        // second half: contract over h1(t-1) — layer1 only
        #pragma unroll
        for (int hp2 = 8; hp2 < 16; ++hp2) {
            ulonglong2 u0 = Wcq[hp2 * 128 + lane];
            ulonglong2 u1 = Wcq[hp2 * 128 + lane + 32];
            ulonglong2 u2 = Wcq[hp2 * 128 + lane + 64];
            ulonglong2 u3 = Wcq[hp2 * 128 + lane + 96];
            #pragma unroll
            for (int r = 0; r < 4; ++r) {
                ulonglong2 hv = ((const ulonglong2*)(hbase + r * 32))[hp2];
                ffma2(a1[r][0], hv.x, u0.x); ffma2(a1[r][0], hv.y, u0.y);
                ffma2(a1[r][1], hv.x, u1.x); ffma2(a1[r][1], hv.y, u1.y);
                ffma2(a1[r][2], hv.x, u2.x); ffma2(a1[r][2], hv.y, u2.y);
                ffma2(a1[r][3], hv.x, u3.x); ffma2(a1[r][3], hv.y, u3.y);
            }
        }

        // ---- A1: h1(t) from a1 (independent of next iter's A0) ----
        #pragma unroll
        for (int r = 0; r < 4; ++r) {
            float gi  = redu(a1[r][0]);
            float gf  = redu(a1[r][1]);
            float gg_ = redu(a1[r][2]);
            float go  = redu(a1[r][3]);
            c1[r]  = sigmf(gf) * c1[r] + sigmf(gi) * tanhfa(gg_);
            h1v[r] = sigmf(go) * tanhfa(c1[r]);
            ((float*)(hbase + r * 32))[32 + lane] = h1v[r];
        }
        __syncwarp();
    }

    #pragma unroll
    for (int r = 0; r < 4; ++r)
        g_comb[(size_t)(b0 + wg * 4 + r) * 1024 + f * 32 + lane] = h1v[r];
}

// ---------------------------------------------------------------------------
// Kernel 3: gaussian head. Block per b.
// ---------------------------------------------------------------------------
__global__ __launch_bounds__(128) void k_head(
    const float* __restrict__ mu_w, const float* __restrict__ mu_b,
    const float* __restrict__ lv_w, const float* __restrict__ lv_b,
    float* __restrict__ out)
{
    __shared__ float smu[4], slv[4];
    const int tid = threadIdx.x, b = blockIdx.x;
    float am = 0.0f, al = 0.0f;
    for (int i = tid; i < 1024; i += 128) {
        float v = g_comb[(size_t)b * 1024 + i];
        am += v * mu_w[i];
        al += v * lv_w[i];
    }
    #pragma unroll
    for (int s = 16; s > 0; s >>= 1) {
        am += __shfl_xor_sync(0xffffffffu, am, s);
        al += __shfl_xor_sync(0xffffffffu, al, s);
    }
    const int wg = tid >> 5, lane = tid & 31;
    if (lane == 0) { smu[wg] = am; slv[wg] = al; }
    __syncthreads();
    if (tid == 0) {
        float mu = smu[0] + smu[1] + smu[2] + smu[3] + mu_b[0];
        float lv = slv[0] + slv[1] + slv[2] + slv[3] + lv_b[0];
        float sg = expf(0.5f * lv);
        out[b]       = mu - 1.96f * sg;
        out[128 + b] = mu;
        out[256 + b] = mu + 1.96f * sg;
        out[384 + b] = lv;
    }
}

// ---------------------------------------------------------------------------
extern "C" void kernel_launch(void* const* d_in, const int* in_sizes, int n_in,
                              void* d_out, int out_size)
{
    const float* x      = (const float*)d_in[0];
    const float* conv_w = (const float*)d_in[1];
    const float* conv_b = (const float*)d_in[2];
    const float* fc1_w  = (const float*)d_in[3];
    const float* fc1_b  = (const float*)d_in[4];
    const float* w_ih0  = (const float*)d_in[5];
    const float* w_ih1  = (const float*)d_in[6];
    const float* w_hh   = (const float*)d_in[7];
    const float* b_lstm = (const float*)d_in[8];
    const float* mu_w   = (const float*)d_in[9];
    const float* mu_b   = (const float*)d_in[10];
    const float* lv_w   = (const float*)d_in[11];
    const float* lv_b   = (const float*)d_in[12];
    float* out = (float*)d_out;

    const int SM_FC1  = (33408 + 16704 + 2048 + 32) * (int)sizeof(float);  // 208,768 B
    const int SM_LSTM = 9408 * (int)sizeof(ull);                           //  75,264 B

    cudaFuncSetAttribute(k_fc1,  cudaFuncAttributeMaxDynamicSharedMemorySize, SM_FC1);
    cudaFuncSetAttribute(k_lstm, cudaFuncAttributeMaxDynamicSharedMemorySize, SM_LSTM);

    k_conv<<<16384, 256>>>(x, conv_w, conv_b);
    k_fc1<<<128, 512, SM_FC1>>>(fc1_w, fc1_b);
    k_lstm<<<128, 256, SM_LSTM>>>(w_ih0, w_ih1, w_hh, b_lstm);
    k_head<<<128, 128>>>(mu_w, mu_b, lv_w, lv_b, out);
}

// round 7
// speedup vs baseline: 1.3810x; 1.0016x over previous
#include <cuda_runtime.h>

// ---------------------------------------------------------------------------
// Groupwise CNN + 32 independent 2-layer LSTMs + gaussian head
// ---------------------------------------------------------------------------

typedef unsigned long long ull;

#define B_    128
#define W_    128
#define FC1_  32
#define H_    32

// scratch (allocation-free rule: __device__ globals)
__device__ float g_pool[16384 * 1040];       // [b*128+w][k*65+j]
__device__ float g_z[FC1_ * 16384];          // [f][b*128+t]  (transposed for lstm)
__device__ float g_comb[B_ * FC1_ * H_];     // [b][f*32+h]

__device__ __forceinline__ void ffma2(ull &d, ull a, ull b) {
    asm("fma.rn.f32x2 %0, %1, %2, %0;" : "+l"(d) : "l"(a), "l"(b));
}
__device__ __forceinline__ float redu(ull a) {
    float lo, hi;
    asm("mov.b64 {%0,%1}, %2;" : "=f"(lo), "=f"(hi) : "l"(a));
    return lo + hi;
}
__device__ __forceinline__ ull pk2(float lo, float hi) {
    ull r;
    asm("mov.b64 %0, {%1,%2};" : "=l"(r) : "f"(lo), "f"(hi));
    return r;
}
__device__ __forceinline__ float sigmf(float x) {
    return __fdividef(1.0f, 1.0f + __expf(-x));
}
__device__ __forceinline__ float tanhfa(float x) {
    return __fdividef(2.0f, 1.0f + __expf(-2.0f * x)) - 1.0f;
}

// ---------------------------------------------------------------------------
// Kernel 1a: conv -> relu -> maxpool. One block per 8 (b,w) rows.
// (R6 bug fixed: parameter loads are strided loops over 256 threads.)
// ---------------------------------------------------------------------------
__global__ __launch_bounds__(256) void k_conv(
    const float* __restrict__ x,
    const float* __restrict__ conv_w, const float* __restrict__ conv_b)
{
    __shared__ float xr[8][130];
    __shared__ float cwv[384], cbv[128];
    const int tid  = threadIdx.x;
    const int row0 = blockIdx.x * 8;           // b*128 + w, 8 rows

    for (int idx = tid; idx < 1024; idx += 256) {
        int rr = idx >> 7, col = idx & 127;
        xr[rr][col + 1] = x[(size_t)(row0 + rr) * 128 + col];
    }
    if (tid < 8) { xr[tid][0] = 0.0f; xr[tid][129] = 0.0f; }
    for (int i = tid; i < 384; i += 256) {
        int rr = i / 48, k = i - rr * 48;
        cwv[i] = conv_w[((row0 + rr) & 127) * 48 + k];
    }
    if (tid < 128) {
        int rr = tid >> 4, k = tid & 15;
        cbv[tid] = conv_b[((row0 + rr) & 127) * 16 + k];
    }
    __syncthreads();

    for (int idx = tid; idx < 8320; idx += 256) {
        int rr = idx / 1040;
        int o  = idx - rr * 1040;
        int k  = o / 65;
        int j  = o - 65 * k;
        float c0 = cwv[rr * 48 + k * 3];
        float c1 = cwv[rr * 48 + k * 3 + 1];
        float c2 = cwv[rr * 48 + k * 3 + 2];
        float bb = cbv[rr * 16 + k];
        const float* xp = xr[rr];
        int p = 2 * j;
        float va = -1e30f, vb = -1e30f;
        if (p > 0)
            va = fmaxf(0.0f, bb + c0 * xp[p - 1] + c1 * xp[p]     + c2 * xp[p + 1]);
        if (p < 128)
            vb = fmaxf(0.0f, bb + c0 * xp[p]     + c1 * xp[p + 1] + c2 * xp[p + 2]);
        g_pool[(size_t)(row0 + rr) * 1040 + o] = fmaxf(va, vb);
    }
}

// ---------------------------------------------------------------------------
// Kernel 1b: fc1 GEMM, 512 threads. Block = 128 rows (8 tiles of 16).
// Warp = (K-chunk cch of 4, row-group g of 4): lane=output, 4 rows/thread.
// Output TRANSPOSED: g_z[f][b*128+t].
// ---------------------------------------------------------------------------
__global__ __launch_bounds__(512) void k_fc1(
    const float* __restrict__ fc1_w, const float* __restrict__ fc1_b)
{
    extern __shared__ float smf[];
    float* Wfp  = smf;                // 32 x 1044 = 33408
    float* sp   = Wfp + 33408;        // 16 x 1044 = 16704
    float* part = sp + 16704;         // 4c x 16r x 32o = 2048
    float* fb   = part + 2048;        // 32

    const int tid = threadIdx.x;

    for (int o = 0; o < 32; ++o)
        for (int c = tid; c < 1040; c += 512)
            Wfp[o * 1044 + c] = fc1_w[o * 1040 + c];
    if (tid < 32) fb[tid] = fc1_b[tid];

    const int wid = tid >> 5, lane = tid & 31;
    const int cch = wid >> 2;          // K-chunk 0..3 (65 quads)
    const int g   = wid & 3;           // row-group 0..3 (4 rows)
    const int qb  = cch * 65;
    const int row_base = blockIdx.x * 128;

    for (int tile = 0; tile < 8; ++tile) {
        const int row0 = row_base + tile * 16;
        __syncthreads();
        for (int idx = tid; idx < 4160; idx += 512) {
            int rr = idx / 260;
            int q  = idx - rr * 260;
            ((float4*)(sp + rr * 1044))[q] =
                ((const float4*)g_pool)[(size_t)(row0 + rr) * 260 + q];
        }
        __syncthreads();

        {
            const ulonglong2* wrow = (const ulonglong2*)(Wfp + lane * 1044) + qb;
            ull acc[4] = {0, 0, 0, 0};
            #pragma unroll 5
            for (int q = 0; q < 65; ++q) {
                ulonglong2 wv = wrow[q];
                #pragma unroll
                for (int r = 0; r < 4; ++r) {
                    ulonglong2 hv = ((const ulonglong2*)(sp + (g * 4 + r) * 1044))[qb + q];
                    ffma2(acc[r], hv.x, wv.x);
                    ffma2(acc[r], hv.y, wv.y);
                }
            }
            #pragma unroll
            for (int r = 0; r < 4; ++r)
                part[(cch * 16 + g * 4 + r) * 32 + lane] = redu(acc[r]);
        }
        __syncthreads();

        {
            int rr = tid >> 5, o = tid & 31;
            float s = fb[o]
                    + part[(0 * 16 + rr) * 32 + o]
                    + part[(1 * 16 + rr) * 32 + o]
                    + part[(2 * 16 + rr) * 32 + o]
                    + part[(3 * 16 + rr) * 32 + o];
            g_z[o * 16384 + row0 + rr] = s;
        }
    }
}

// ---------------------------------------------------------------------------
// Kernel 2: the LSTM. Block = (f, 32-batch chunk), 256 threads (8 warps).
// warp <-> 4 cells; lane = hidden index (owns gates lane,+32,+64,+96).
// Pipelined + REORDERED: per step
//   (1) a1 partial over h1(t-1)   [independent of A0 -> fills its MUFU bubble]
//   (2) A0: h0(t) activations
//   (3) shared-h0 GEMM: a1 finish + a0(t+1) start  [W0 groups 0,1 in REGISTERS]
//   (4) A1: h1(t) activations
// ---------------------------------------------------------------------------
__global__ __launch_bounds__(256, 1) void k_lstm(
    const float* __restrict__ w_ih0, const float* __restrict__ w_ih1,
    const float* __restrict__ w_hh,  const float* __restrict__ b_lstm)
{
    extern __shared__ ull sm2[];
    ulonglong2* W0q = (ulonglong2*)sm2;            // [8 hp2][128 g]   16KB
    ulonglong2* Wcq = (ulonglong2*)(sm2 + 2048);   // [16 hp2][128 g]  32KB
    ull*   hcat = sm2 + 6144;                      // [32 cells][32 pairs] 8KB
    float* zb   = (float*)(sm2 + 7168);            // [32 b][128 t]    16KB
    float* wi0  = zb + 4096;                       // 128
    float* bs0  = wi0 + 128;                       // 128
    float* bs1  = bs0 + 128;                       // 128

    const int tid = threadIdx.x;
    const int f   = blockIdx.x & 31;
    const int b0  = (blockIdx.x >> 5) * 32;

    const float* whh0 = w_hh  + (size_t)f        * 4096;  // [g][h]
    const float* whh1 = w_hh  + (size_t)(32 + f) * 4096;
    const float* wi1  = w_ih1 + (size_t)f        * 4096;

    for (int idx = tid; idx < 1024; idx += 256) {
        int hp2 = idx >> 7, gg = idx & 127;
        float4 v = *(const float4*)(whh0 + gg * 32 + 4 * hp2);
        W0q[idx] = make_ulonglong2(pk2(v.x, v.y), pk2(v.z, v.w));
    }
    for (int idx = tid; idx < 2048; idx += 256) {
        int hp2 = idx >> 7, gg = idx & 127;
        float4 v = (hp2 < 8) ? *(const float4*)(wi1  + gg * 32 + 4 * hp2)
                             : *(const float4*)(whh1 + gg * 32 + 4 * (hp2 - 8));
        Wcq[idx] = make_ulonglong2(pk2(v.x, v.y), pk2(v.z, v.w));
    }
    if (tid < 128) {
        wi0[tid] = w_ih0[f * 128 + tid];
        bs0[tid] = b_lstm[f * 128 + tid];
        bs1[tid] = b_lstm[(32 + f) * 128 + tid];
    }
    for (int idx = tid; idx < 4096; idx += 256)
        zb[idx] = g_z[f * 16384 + b0 * 128 + idx];
    for (int idx = tid; idx < 1024; idx += 256) hcat[idx] = 0ull;
    __syncthreads();

    const int wg = tid >> 5, lane = tid & 31;
    ull* hbase = hcat + (wg * 4) * 32;             // 4 cells x 32 pairs

    // per-lane hoisted scalars
    float wi0g[4], bs0g[4], bs1g[4];
    #pragma unroll
    for (int gg = 0; gg < 4; ++gg) {
        wi0g[gg] = wi0[lane + 32 * gg];
        bs0g[gg] = bs0[lane + 32 * gg];
        bs1g[gg] = bs1[lane + 32 * gg];
    }

    // layer0 weights for gate groups 0,1 held in registers (loop-invariant)
    ulonglong2 V0[8], V1[8];
    #pragma unroll
    for (int hp2 = 0; hp2 < 8; ++hp2) {
        V0[hp2] = W0q[hp2 * 128 + lane];
        V1[hp2] = W0q[hp2 * 128 + lane + 32];
    }

    float c0[4] = {0, 0, 0, 0};
    float c1[4] = {0, 0, 0, 0};
    float h1v[4];
    const float* zw = zb + (wg * 4) * 128;

    // prologue: gates0(t=0) = x(0)*wi0 + b0  (h0(-1)=0)
    ull a0[4][4];
    #pragma unroll
    for (int r = 0; r < 4; ++r) {
        float xv = zw[r * 128];
        #pragma unroll
        for (int gg = 0; gg < 4; ++gg)
            a0[r][gg] = pk2(fmaf(xv, wi0g[gg], bs0g[gg]), 0.0f);
    }

    #pragma unroll 2
    for (int t = 0; t < 128; ++t) {
        // ---- (1) a1 partial: bias + contraction over h1(t-1) (hp2 8..15) ----
        ull a1[4][4];
        #pragma unroll
        for (int r = 0; r < 4; ++r)
            #pragma unroll
            for (int gg = 0; gg < 4; ++gg)
                a1[r][gg] = pk2(bs1g[gg], 0.0f);
        #pragma unroll
        for (int hp2 = 8; hp2 < 16; ++hp2) {
            ulonglong2 u0 = Wcq[hp2 * 128 + lane];
            ulonglong2 u1 = Wcq[hp2 * 128 + lane + 32];
            ulonglong2 u2 = Wcq[hp2 * 128 + lane + 64];
            ulonglong2 u3 = Wcq[hp2 * 128 + lane + 96];
            #pragma unroll
            for (int r = 0; r < 4; ++r) {
                ulonglong2 hv = ((const ulonglong2*)(hbase + r * 32))[hp2];
                ffma2(a1[r][0], hv.x, u0.x); ffma2(a1[r][0], hv.y, u0.y);
                ffma2(a1[r][1], hv.x, u1.x); ffma2(a1[r][1], hv.y, u1.y);
                ffma2(a1[r][2], hv.x, u2.x); ffma2(a1[r][2], hv.y, u2.y);
                ffma2(a1[r][3], hv.x, u3.x); ffma2(a1[r][3], hv.y, u3.y);
            }
        }

        // ---- (2) A0: h0(t) from a0 ----
        #pragma unroll
        for (int r = 0; r < 4; ++r) {
            float gi  = redu(a0[r][0]);
            float gf  = redu(a0[r][1]);
            float gg_ = redu(a0[r][2]);
            float go  = redu(a0[r][3]);
            c0[r] = sigmf(gf) * c0[r] + sigmf(gi) * tanhfa(gg_);
            ((float*)(hbase + r * 32))[lane] = sigmf(go) * tanhfa(c0[r]);
        }
        __syncwarp();

        // ---- (3) shared-h0 GEMM: finish a1, start a0(t+1) ----
        {
            const int tn = (t + 1) & 127;
            #pragma unroll
            for (int r = 0; r < 4; ++r) {
                float xv = zw[r * 128 + tn];
                #pragma unroll
                for (int gg = 0; gg < 4; ++gg)
                    a0[r][gg] = pk2(fmaf(xv, wi0g[gg], bs0g[gg]), 0.0f);
            }
        }
        #pragma unroll
        for (int hp2 = 0; hp2 < 8; ++hp2) {
            ulonglong2 u0 = Wcq[hp2 * 128 + lane];
            ulonglong2 u1 = Wcq[hp2 * 128 + lane + 32];
            ulonglong2 u2 = Wcq[hp2 * 128 + lane + 64];
            ulonglong2 u3 = Wcq[hp2 * 128 + lane + 96];
            ulonglong2 v2 = W0q[hp2 * 128 + lane + 64];
            ulonglong2 v3 = W0q[hp2 * 128 + lane + 96];
            #pragma unroll
            for (int r = 0; r < 4; ++r) {
                ulonglong2 hv = ((const ulonglong2*)(hbase + r * 32))[hp2];
                ffma2(a1[r][0], hv.x, u0.x); ffma2(a1[r][0], hv.y, u0.y);
                ffma2(a1[r][1], hv.x, u1.x); ffma2(a1[r][1], hv.y, u1.y);
                ffma2(a1[r][2], hv.x, u2.x); ffma2(a1[r][2], hv.y, u2.y);
                ffma2(a1[r][3], hv.x, u3.x); ffma2(a1[r][3], hv.y, u3.y);
                ffma2(a0[r][0], hv.x, V0[hp2].x); ffma2(a0[r][0], hv.y, V0[hp2].y);
                ffma2(a0[r][1], hv.x, V1[hp2].x); ffma2(a0[r][1], hv.y, V1[hp2].y);
                ffma2(a0[r][2], hv.x, v2.x); ffma2(a0[r][2], hv.y, v2.y);
                ffma2(a0[r][3], hv.x, v3.x); ffma2(a0[r][3], hv.y, v3.y);
            }
        }

        // ---- (4) A1: h1(t) from a1 ----
        #pragma unroll
        for (int r = 0; r < 4; ++r) {
            float gi  = redu(a1[r][0]);
            float gf  = redu(a1[r][1]);
            float gg_ = redu(a1[r][2]);
            float go  = redu(a1[r][3]);
            c1[r]  = sigmf(gf) * c1[r] + sigmf(gi) * tanhfa(gg_);
            h1v[r] = sigmf(go) * tanhfa(c1[r]);
            ((float*)(hbase + r * 32))[32 + lane] = h1v[r];
        }
        __syncwarp();
    }

    #pragma unroll
    for (int r = 0; r < 4; ++r)
        g_comb[(size_t)(b0 + wg * 4 + r) * 1024 + f * 32 + lane] = h1v[r];
}

// ---------------------------------------------------------------------------
// Kernel 3: gaussian head. Block per b.
// ---------------------------------------------------------------------------
__global__ __launch_bounds__(128) void k_head(
    const float* __restrict__ mu_w, const float* __restrict__ mu_b,
    const float* __restrict__ lv_w, const float* __restrict__ lv_b,
    float* __restrict__ out)
{
    __shared__ float smu[4], slv[4];
    const int tid = threadIdx.x, b = blockIdx.x;
    float am = 0.0f, al = 0.0f;
    for (int i = tid; i < 1024; i += 128) {
        float v = g_comb[(size_t)b * 1024 + i];
        am += v * mu_w[i];
        al += v * lv_w[i];
    }
    #pragma unroll
    for (int s = 16; s > 0; s >>= 1) {
        am += __shfl_xor_sync(0xffffffffu, am, s);
        al += __shfl_xor_sync(0xffffffffu, al, s);
    }
    const int wg = tid >> 5, lane = tid & 31;
    if (lane == 0) { smu[wg] = am; slv[wg] = al; }
    __syncthreads();
    if (tid == 0) {
        float mu = smu[0] + smu[1] + smu[2] + smu[3] + mu_b[0];
        float lv = slv[0] + slv[1] + slv[2] + slv[3] + lv_b[0];
        float sg = expf(0.5f * lv);
        out[b]       = mu - 1.96f * sg;
        out[128 + b] = mu;
        out[256 + b] = mu + 1.96f * sg;
        out[384 + b] = lv;
    }
}

// ---------------------------------------------------------------------------
extern "C" void kernel_launch(void* const* d_in, const int* in_sizes, int n_in,
                              void* d_out, int out_size)
{
    const float* x      = (const float*)d_in[0];
    const float* conv_w = (const float*)d_in[1];
    const float* conv_b = (const float*)d_in[2];
    const float* fc1_w  = (const float*)d_in[3];
    const float* fc1_b  = (const float*)d_in[4];
    const float* w_ih0  = (const float*)d_in[5];
    const float* w_ih1  = (const float*)d_in[6];
    const float* w_hh   = (const float*)d_in[7];
    const float* b_lstm = (const float*)d_in[8];
    const float* mu_w   = (const float*)d_in[9];
    const float* mu_b   = (const float*)d_in[10];
    const float* lv_w   = (const float*)d_in[11];
    const float* lv_b   = (const float*)d_in[12];
    float* out = (float*)d_out;

    const int SM_FC1  = (33408 + 16704 + 2048 + 32) * (int)sizeof(float);  // 208,768 B
    const int SM_LSTM = 9408 * (int)sizeof(ull);                           //  75,264 B

    cudaFuncSetAttribute(k_fc1,  cudaFuncAttributeMaxDynamicSharedMemorySize, SM_FC1);
    cudaFuncSetAttribute(k_lstm, cudaFuncAttributeMaxDynamicSharedMemorySize, SM_LSTM);

    k_conv<<<2048, 256>>>(x, conv_w, conv_b);
    k_fc1<<<128, 512, SM_FC1>>>(fc1_w, fc1_b);
    k_lstm<<<128, 256, SM_LSTM>>>(w_ih0, w_ih1, w_hh, b_lstm);
    k_head<<<128, 128>>>(mu_w, mu_b, lv_w, lv_b, out);
}

// round 8
// speedup vs baseline: 1.3913x; 1.0075x over previous
#include <cuda_runtime.h>

// ---------------------------------------------------------------------------
// Groupwise CNN + 32 independent 2-layer LSTMs + gaussian head
// ---------------------------------------------------------------------------

typedef unsigned long long ull;

#define B_    128
#define W_    128
#define FC1_  32
#define H_    32

// scratch (allocation-free rule: __device__ globals)
__device__ float g_z[FC1_ * 16384];          // [f][b*128+t]  (transposed for lstm)
__device__ float g_comb[B_ * FC1_ * H_];     // [b][f*32+h]

__device__ __forceinline__ void ffma2(ull &d, ull a, ull b) {
    asm("fma.rn.f32x2 %0, %1, %2, %0;" : "+l"(d) : "l"(a), "l"(b));
}
__device__ __forceinline__ float redu(ull a) {
    float lo, hi;
    asm("mov.b64 {%0,%1}, %2;" : "=f"(lo), "=f"(hi) : "l"(a));
    return lo + hi;
}
__device__ __forceinline__ ull pk2(float lo, float hi) {
    ull r;
    asm("mov.b64 %0, {%1,%2};" : "=l"(r) : "f"(lo), "f"(hi));
    return r;
}
__device__ __forceinline__ float sigmf(float x) {
    return __fdividef(1.0f, 1.0f + __expf(-x));
}
__device__ __forceinline__ float tanhfa(float x) {
    return __fdividef(2.0f, 1.0f + __expf(-2.0f * x)) - 1.0f;
}

// ---------------------------------------------------------------------------
// Kernel 1: FUSED conv -> relu -> maxpool -> fc1 GEMM. One block per batch b,
// 512 threads, 8 phases of 16 w-rows. No gmem intermediate: pooled tile is
// produced directly in the smem GEMM operand (rows padded to 1044 floats,
// quad-aligned for LDS.128).
// GEMM: warp = (K-chunk cch of 4, row-group g of 4); lane = output o;
// 4 rows/thread; 4 K-chunk partials combined via smem.
// Output TRANSPOSED: g_z[f][b*128+t] (contiguous for k_lstm).
// ---------------------------------------------------------------------------
__global__ __launch_bounds__(512) void k_convfc(
    const float* __restrict__ x,
    const float* __restrict__ conv_w, const float* __restrict__ conv_b,
    const float* __restrict__ fc1_w,  const float* __restrict__ fc1_b)
{
    extern __shared__ float smf[];
    float* Wfp  = smf;                // 32 x 1044 = 33408
    float* sp   = Wfp + 33408;        // 16 x 1044 = 16704  (pooled tile)
    float* part = sp + 16704;         // 4c x 16r x 32o = 2048
    float* xr   = part + 2048;        // 16 x 132 = 2112
    float* cw   = xr + 2112;          // 768
    float* cb   = cw + 768;           // 256
    float* fb   = cb + 256;           // 32

    const int tid = threadIdx.x;
    const int b   = blockIdx.x;

    // load fc1 weights (padded rows) + bias
    for (int o = 0; o < 32; ++o)
        for (int c = tid; c < 1040; c += 512)
            Wfp[o * 1044 + c] = fc1_w[o * 1040 + c];
    if (tid < 32) fb[tid] = fc1_b[tid];

    const int wid = tid >> 5, lane = tid & 31;
    const int cch = wid >> 2;          // K-chunk 0..3 (65 quads)
    const int g   = wid & 3;           // row-group 0..3 (4 rows)
    const int qb  = cch * 65;

    for (int ph = 0; ph < 8; ++ph) {
        const int w0 = ph * 16;

        // ---- stage x rows + conv params for 16 w ----
        for (int idx = tid; idx < 2048; idx += 512) {
            int row = idx >> 7, col = idx & 127;
            xr[row * 132 + col + 1] = x[(size_t)b * 16384 + (w0 + row) * 128 + col];
        }
        if (tid < 16) { xr[tid * 132] = 0.0f; xr[tid * 132 + 129] = 0.0f; }
        for (int i = tid; i < 768; i += 512) cw[i] = conv_w[w0 * 48 + i];
        if (tid < 256) cb[tid] = conv_b[w0 * 16 + tid];
        __syncthreads();

        // ---- conv + relu + maxpool directly into GEMM operand sp ----
        for (int idx = tid; idx < 16640; idx += 512) {
            int row = idx / 1040;
            int rem = idx - row * 1040;
            int k   = rem / 65;
            int j   = rem - k * 65;
            float c0w = cw[row * 48 + k * 3];
            float c1w = cw[row * 48 + k * 3 + 1];
            float c2w = cw[row * 48 + k * 3 + 2];
            float bb  = cb[row * 16 + k];
            const float* xp = xr + row * 132;
            int p = 2 * j;
            float va = -1e30f, vb = -1e30f;
            if (p > 0)
                va = fmaxf(0.0f, bb + c0w * xp[p - 1] + c1w * xp[p]     + c2w * xp[p + 1]);
            if (p < 128)
                vb = fmaxf(0.0f, bb + c0w * xp[p]     + c1w * xp[p + 1] + c2w * xp[p + 2]);
            sp[row * 1044 + rem] = fmaxf(va, vb);
        }
        __syncthreads();

        // ---- GEMM over K-chunk: 4 rows per thread ----
        {
            const ulonglong2* wrow = (const ulonglong2*)(Wfp + lane * 1044) + qb;
            ull acc[4] = {0, 0, 0, 0};
            #pragma unroll 5
            for (int q = 0; q < 65; ++q) {
                ulonglong2 wv = wrow[q];
                #pragma unroll
                for (int r = 0; r < 4; ++r) {
                    ulonglong2 hv = ((const ulonglong2*)(sp + (g * 4 + r) * 1044))[qb + q];
                    ffma2(acc[r], hv.x, wv.x);
                    ffma2(acc[r], hv.y, wv.y);
                }
            }
            #pragma unroll
            for (int r = 0; r < 4; ++r)
                part[(cch * 16 + g * 4 + r) * 32 + lane] = redu(acc[r]);
        }
        __syncthreads();

        // ---- combine partials + bias; transposed store ----
        {
            int rr = tid >> 5, o = tid & 31;
            float s = fb[o]
                    + part[(0 * 16 + rr) * 32 + o]
                    + part[(1 * 16 + rr) * 32 + o]
                    + part[(2 * 16 + rr) * 32 + o]
                    + part[(3 * 16 + rr) * 32 + o];
            g_z[o * 16384 + b * 128 + w0 + rr] = s;
        }
        // next phase's staging writes (xr/cw/cb) are safe without an extra
        // barrier: every thread reaching them has passed the GEMM->combine
        // sync, and conv (last reader of xr/cw/cb) completed before it.
    }
}

// ---------------------------------------------------------------------------
// Kernel 2: the LSTM (unchanged from R7 best). Block = (f, 32-batch chunk),
// 256 threads (8 warps); warp <-> 4 cells; lane = hidden index.
// ---------------------------------------------------------------------------
__global__ __launch_bounds__(256, 1) void k_lstm(
    const float* __restrict__ w_ih0, const float* __restrict__ w_ih1,
    const float* __restrict__ w_hh,  const float* __restrict__ b_lstm)
{
    extern __shared__ ull sm2[];
    ulonglong2* W0q = (ulonglong2*)sm2;            // [8 hp2][128 g]   16KB
    ulonglong2* Wcq = (ulonglong2*)(sm2 + 2048);   // [16 hp2][128 g]  32KB
    ull*   hcat = sm2 + 6144;                      // [32 cells][32 pairs] 8KB
    float* zb   = (float*)(sm2 + 7168);            // [32 b][128 t]    16KB
    float* wi0  = zb + 4096;                       // 128
    float* bs0  = wi0 + 128;                       // 128
    float* bs1  = bs0 + 128;                       // 128

    const int tid = threadIdx.x;
    const int f   = blockIdx.x & 31;
    const int b0  = (blockIdx.x >> 5) * 32;

    const float* whh0 = w_hh  + (size_t)f        * 4096;  // [g][h]
    const float* whh1 = w_hh  + (size_t)(32 + f) * 4096;
    const float* wi1  = w_ih1 + (size_t)f        * 4096;

    for (int idx = tid; idx < 1024; idx += 256) {
        int hp2 = idx >> 7, gg = idx & 127;
        float4 v = *(const float4*)(whh0 + gg * 32 + 4 * hp2);
        W0q[idx] = make_ulonglong2(pk2(v.x, v.y), pk2(v.z, v.w));
    }
    for (int idx = tid; idx < 2048; idx += 256) {
        int hp2 = idx >> 7, gg = idx & 127;
        float4 v = (hp2 < 8) ? *(const float4*)(wi1  + gg * 32 + 4 * hp2)
                             : *(const float4*)(whh1 + gg * 32 + 4 * (hp2 - 8));
        Wcq[idx] = make_ulonglong2(pk2(v.x, v.y), pk2(v.z, v.w));
    }
    if (tid < 128) {
        wi0[tid] = w_ih0[f * 128 + tid];
        bs0[tid] = b_lstm[f * 128 + tid];
        bs1[tid] = b_lstm[(32 + f) * 128 + tid];
    }
    for (int idx = tid; idx < 4096; idx += 256)
        zb[idx] = g_z[f * 16384 + b0 * 128 + idx];
    for (int idx = tid; idx < 1024; idx += 256) hcat[idx] = 0ull;
    __syncthreads();

    const int wg = tid >> 5, lane = tid & 31;
    ull* hbase = hcat + (wg * 4) * 32;             // 4 cells x 32 pairs

    float wi0g[4], bs0g[4], bs1g[4];
    #pragma unroll
    for (int gg = 0; gg < 4; ++gg) {
        wi0g[gg] = wi0[lane + 32 * gg];
        bs0g[gg] = bs0[lane + 32 * gg];
        bs1g[gg] = bs1[lane + 32 * gg];
    }

    // layer0 weights for gate groups 0,1 held in registers (loop-invariant)
    ulonglong2 V0[8], V1[8];
    #pragma unroll
    for (int hp2 = 0; hp2 < 8; ++hp2) {
        V0[hp2] = W0q[hp2 * 128 + lane];
        V1[hp2] = W0q[hp2 * 128 + lane + 32];
    }

    float c0[4] = {0, 0, 0, 0};
    float c1[4] = {0, 0, 0, 0};
    float h1v[4];
    const float* zw = zb + (wg * 4) * 128;

    // prologue: gates0(t=0) = x(0)*wi0 + b0  (h0(-1)=0)
    ull a0[4][4];
    #pragma unroll
    for (int r = 0; r < 4; ++r) {
        float xv = zw[r * 128];
        #pragma unroll
        for (int gg = 0; gg < 4; ++gg)
            a0[r][gg] = pk2(fmaf(xv, wi0g[gg], bs0g[gg]), 0.0f);
    }

    #pragma unroll 2
    for (int t = 0; t < 128; ++t) {
        // ---- (1) a1 partial: bias + contraction over h1(t-1) (hp2 8..15) ----
        ull a1[4][4];
        #pragma unroll
        for (int r = 0; r < 4; ++r)
            #pragma unroll
            for (int gg = 0; gg < 4; ++gg)
                a1[r][gg] = pk2(bs1g[gg], 0.0f);
        #pragma unroll
        for (int hp2 = 8; hp2 < 16; ++hp2) {
            ulonglong2 u0 = Wcq[hp2 * 128 + lane];
            ulonglong2 u1 = Wcq[hp2 * 128 + lane + 32];
            ulonglong2 u2 = Wcq[hp2 * 128 + lane + 64];
            ulonglong2 u3 = Wcq[hp2 * 128 + lane + 96];
            #pragma unroll
            for (int r = 0; r < 4; ++r) {
                ulonglong2 hv = ((const ulonglong2*)(hbase + r * 32))[hp2];
                ffma2(a1[r][0], hv.x, u0.x); ffma2(a1[r][0], hv.y, u0.y);
                ffma2(a1[r][1], hv.x, u1.x); ffma2(a1[r][1], hv.y, u1.y);
                ffma2(a1[r][2], hv.x, u2.x); ffma2(a1[r][2], hv.y, u2.y);
                ffma2(a1[r][3], hv.x, u3.x); ffma2(a1[r][3], hv.y, u3.y);
            }
        }

        // ---- (2) A0: h0(t) from a0 ----
        #pragma unroll
        for (int r = 0; r < 4; ++r) {
            float gi  = redu(a0[r][0]);
            float gf  = redu(a0[r][1]);
            float gg_ = redu(a0[r][2]);
            float go  = redu(a0[r][3]);
            c0[r] = sigmf(gf) * c0[r] + sigmf(gi) * tanhfa(gg_);
            ((float*)(hbase + r * 32))[lane] = sigmf(go) * tanhfa(c0[r]);
        }
        __syncwarp();

        // ---- (3) shared-h0 GEMM: finish a1, start a0(t+1) ----
        {
            const int tn = (t + 1) & 127;
            #pragma unroll
            for (int r = 0; r < 4; ++r) {
                float xv = zw[r * 128 + tn];
                #pragma unroll
                for (int gg = 0; gg < 4; ++gg)
                    a0[r][gg] = pk2(fmaf(xv, wi0g[gg], bs0g[gg]), 0.0f);
            }
        }
        #pragma unroll
        for (int hp2 = 0; hp2 < 8; ++hp2) {
            ulonglong2 u0 = Wcq[hp2 * 128 + lane];
            ulonglong2 u1 = Wcq[hp2 * 128 + lane + 32];
            ulonglong2 u2 = Wcq[hp2 * 128 + lane + 64];
            ulonglong2 u3 = Wcq[hp2 * 128 + lane + 96];
            ulonglong2 v2 = W0q[hp2 * 128 + lane + 64];
            ulonglong2 v3 = W0q[hp2 * 128 + lane + 96];
            #pragma unroll
            for (int r = 0; r < 4; ++r) {
                ulonglong2 hv = ((const ulonglong2*)(hbase + r * 32))[hp2];
                ffma2(a1[r][0], hv.x, u0.x); ffma2(a1[r][0], hv.y, u0.y);
                ffma2(a1[r][1], hv.x, u1.x); ffma2(a1[r][1], hv.y, u1.y);
                ffma2(a1[r][2], hv.x, u2.x); ffma2(a1[r][2], hv.y, u2.y);
                ffma2(a1[r][3], hv.x, u3.x); ffma2(a1[r][3], hv.y, u3.y);
                ffma2(a0[r][0], hv.x, V0[hp2].x); ffma2(a0[r][0], hv.y, V0[hp2].y);
                ffma2(a0[r][1], hv.x, V1[hp2].x); ffma2(a0[r][1], hv.y, V1[hp2].y);
                ffma2(a0[r][2], hv.x, v2.x); ffma2(a0[r][2], hv.y, v2.y);
                ffma2(a0[r][3], hv.x, v3.x); ffma2(a0[r][3], hv.y, v3.y);
            }
        }

        // ---- (4) A1: h1(t) from a1 ----
        #pragma unroll
        for (int r = 0; r < 4; ++r) {
            float gi  = redu(a1[r][0]);
            float gf  = redu(a1[r][1]);
            float gg_ = redu(a1[r][2]);
            float go  = redu(a1[r][3]);
            c1[r]  = sigmf(gf) * c1[r] + sigmf(gi) * tanhfa(gg_);
            h1v[r] = sigmf(go) * tanhfa(c1[r]);
            ((float*)(hbase + r * 32))[32 + lane] = h1v[r];
        }
        __syncwarp();
    }

    #pragma unroll
    for (int r = 0; r < 4; ++r)
        g_comb[(size_t)(b0 + wg * 4 + r) * 1024 + f * 32 + lane] = h1v[r];
}

// ---------------------------------------------------------------------------
// Kernel 3: gaussian head. Block per b.
// ---------------------------------------------------------------------------
__global__ __launch_bounds__(128) void k_head(
    const float* __restrict__ mu_w, const float* __restrict__ mu_b,
    const float* __restrict__ lv_w, const float* __restrict__ lv_b,
    float* __restrict__ out)
{
    __shared__ float smu[4], slv[4];
    const int tid = threadIdx.x, b = blockIdx.x;
    float am = 0.0f, al = 0.0f;
    for (int i = tid; i < 1024; i += 128) {
        float v = g_comb[(size_t)b * 1024 + i];
        am += v * mu_w[i];
        al += v * lv_w[i];
    }
    #pragma unroll
    for (int s = 16; s > 0; s >>= 1) {
        am += __shfl_xor_sync(0xffffffffu, am, s);
        al += __shfl_xor_sync(0xffffffffu, al, s);
    }
    const int wg = tid >> 5, lane = tid & 31;
    if (lane == 0) { smu[wg] = am; slv[wg] = al; }
    __syncthreads();
    if (tid == 0) {
        float mu = smu[0] + smu[1] + smu[2] + smu[3] + mu_b[0];
        float lv = slv[0] + slv[1] + slv[2] + slv[3] + lv_b[0];
        float sg = expf(0.5f * lv);
        out[b]       = mu - 1.96f * sg;
        out[128 + b] = mu;
        out[256 + b] = mu + 1.96f * sg;
        out[384 + b] = lv;
    }
}

// ---------------------------------------------------------------------------
extern "C" void kernel_launch(void* const* d_in, const int* in_sizes, int n_in,
                              void* d_out, int out_size)
{
    const float* x      = (const float*)d_in[0];
    const float* conv_w = (const float*)d_in[1];
    const float* conv_b = (const float*)d_in[2];
    const float* fc1_w  = (const float*)d_in[3];
    const float* fc1_b  = (const float*)d_in[4];
    const float* w_ih0  = (const float*)d_in[5];
    const float* w_ih1  = (const float*)d_in[6];
    const float* w_hh   = (const float*)d_in[7];
    const float* b_lstm = (const float*)d_in[8];
    const float* mu_w   = (const float*)d_in[9];
    const float* mu_b   = (const float*)d_in[10];
    const float* lv_w   = (const float*)d_in[11];
    const float* lv_b   = (const float*)d_in[12];
    float* out = (float*)d_out;

    const int SM_CF   = (33408 + 16704 + 2048 + 2112 + 768 + 256 + 32)
                        * (int)sizeof(float);                              // 221,312 B
    const int SM_LSTM = 9408 * (int)sizeof(ull);                           //  75,264 B

    cudaFuncSetAttribute(k_convfc, cudaFuncAttributeMaxDynamicSharedMemorySize, SM_CF);
    cudaFuncSetAttribute(k_lstm,   cudaFuncAttributeMaxDynamicSharedMemorySize, SM_LSTM);

    k_convfc<<<128, 512, SM_CF>>>(x, conv_w, conv_b, fc1_w, fc1_b);
    k_lstm<<<128, 256, SM_LSTM>>>(w_ih0, w_ih1, w_hh, b_lstm);
    k_head<<<128, 128>>>(mu_w, mu_b, lv_w, lv_b, out);
}

// round 9
// speedup vs baseline: 1.4770x; 1.0616x over previous
#include <cuda_runtime.h>

// ---------------------------------------------------------------------------
// Groupwise CNN + 32 independent 2-layer LSTMs + gaussian head
// ---------------------------------------------------------------------------

typedef unsigned long long ull;

#define B_    128
#define W_    128
#define FC1_  32
#define H_    32

// scratch (allocation-free rule: __device__ globals)
__device__ float g_z[FC1_ * 16384];          // [f][b*128+t]  (transposed for lstm)
__device__ float g_comb[B_ * FC1_ * H_];     // [b][f*32+h]

__device__ __forceinline__ void ffma2(ull &d, ull a, ull b) {
    asm("fma.rn.f32x2 %0, %1, %2, %0;" : "+l"(d) : "l"(a), "l"(b));
}
__device__ __forceinline__ float redu(ull a) {
    float lo, hi;
    asm("mov.b64 {%0,%1}, %2;" : "=f"(lo), "=f"(hi) : "l"(a));
    return lo + hi;
}
__device__ __forceinline__ ull pk2(float lo, float hi) {
    ull r;
    asm("mov.b64 %0, {%1,%2};" : "=l"(r) : "f"(lo), "f"(hi));
    return r;
}
__device__ __forceinline__ float sigmf(float x) {
    return __fdividef(1.0f, 1.0f + __expf(-x));
}
__device__ __forceinline__ float tanhfa(float x) {
    return __fdividef(2.0f, 1.0f + __expf(-2.0f * x)) - 1.0f;
}

// ---------------------------------------------------------------------------
// Kernel 1: FUSED conv -> relu -> maxpool -> fc1 GEMM. One block per batch b,
// 512 threads, 8 phases of 16 w-rows. Pooled tile produced directly in the
// smem GEMM operand (rows padded to 1044 floats, quad-aligned for LDS.128).
// Conv mapping is DIVISION-FREE: 512 threads = 16 rows x 16 kernels x 2
// halves; conv weights hoisted to registers.
// GEMM: warp = (K-chunk cch of 4, row-group g of 4); lane = output o;
// 4 rows/thread; 4 K-chunk partials combined via smem.
// Output TRANSPOSED: g_z[f][b*128+t] (contiguous for k_lstm).
// ---------------------------------------------------------------------------
__global__ __launch_bounds__(512) void k_convfc(
    const float* __restrict__ x,
    const float* __restrict__ conv_w, const float* __restrict__ conv_b,
    const float* __restrict__ fc1_w,  const float* __restrict__ fc1_b)
{
    extern __shared__ float smf[];
    float* Wfp  = smf;                // 32 x 1044 = 33408
    float* sp   = Wfp + 33408;        // 16 x 1044 = 16704  (pooled tile)
    float* part = sp + 16704;         // 4c x 16r x 32o = 2048
    float* xr   = part + 2048;        // 16 x 132 = 2112
    float* cw   = xr + 2112;          // 768
    float* cb   = cw + 768;           // 256
    float* fb   = cb + 256;           // 32

    const int tid = threadIdx.x;
    const int b   = blockIdx.x;

    // load fc1 weights (padded rows) + bias
    for (int o = 0; o < 32; ++o)
        for (int c = tid; c < 1040; c += 512)
            Wfp[o * 1044 + c] = fc1_w[o * 1040 + c];
    if (tid < 32) fb[tid] = fc1_b[tid];

    const int wid = tid >> 5, lane = tid & 31;
    // GEMM mapping
    const int cch = wid >> 2;          // K-chunk 0..3 (65 quads)
    const int g   = wid & 3;           // row-group 0..3 (4 rows)
    const int qb  = cch * 65;
    // conv mapping (division-free): 16 rows x 16 k x 2 halves = 512
    const int crow = tid >> 5;         // 0..15
    const int ck   = (tid >> 1) & 15;  // 0..15
    const int chal = tid & 1;

    for (int ph = 0; ph < 8; ++ph) {
        const int w0 = ph * 16;

        // ---- stage x rows + conv params for 16 w ----
        for (int idx = tid; idx < 2048; idx += 512) {
            int row = idx >> 7, col = idx & 127;
            xr[row * 132 + col + 1] = x[(size_t)b * 16384 + (w0 + row) * 128 + col];
        }
        if (tid < 16) { xr[tid * 132] = 0.0f; xr[tid * 132 + 129] = 0.0f; }
        for (int i = tid; i < 768; i += 512) cw[i] = conv_w[w0 * 48 + i];
        if (tid < 256) cb[tid] = conv_b[w0 * 16 + tid];
        __syncthreads();

        // ---- conv + relu + maxpool into GEMM operand sp (no divisions) ----
        {
            const float c0w = cw[crow * 48 + ck * 3];
            const float c1w = cw[crow * 48 + ck * 3 + 1];
            const float c2w = cw[crow * 48 + ck * 3 + 2];
            const float bb  = cb[crow * 16 + ck];
            const float* xp = xr + crow * 132;
            float* pp = sp + crow * 1044 + ck * 65;
            const int j0 = chal ? 33 : 0;
            const int j1 = chal ? 65 : 33;
            for (int j = j0; j < j1; ++j) {
                int p = 2 * j;
                float va = -1e30f, vb = -1e30f;
                if (p > 0)
                    va = fmaxf(0.0f, bb + c0w * xp[p - 1] + c1w * xp[p]     + c2w * xp[p + 1]);
                if (p < 128)
                    vb = fmaxf(0.0f, bb + c0w * xp[p]     + c1w * xp[p + 1] + c2w * xp[p + 2]);
                pp[j] = fmaxf(va, vb);
            }
        }
        __syncthreads();

        // ---- GEMM over K-chunk: 4 rows per thread ----
        {
            const ulonglong2* wrow = (const ulonglong2*)(Wfp + lane * 1044) + qb;
            ull acc[4] = {0, 0, 0, 0};
            #pragma unroll 5
            for (int q = 0; q < 65; ++q) {
                ulonglong2 wv = wrow[q];
                #pragma unroll
                for (int r = 0; r < 4; ++r) {
                    ulonglong2 hv = ((const ulonglong2*)(sp + (g * 4 + r) * 1044))[qb + q];
                    ffma2(acc[r], hv.x, wv.x);
                    ffma2(acc[r], hv.y, wv.y);
                }
            }
            #pragma unroll
            for (int r = 0; r < 4; ++r)
                part[(cch * 16 + g * 4 + r) * 32 + lane] = redu(acc[r]);
        }
        __syncthreads();

        // ---- combine partials + bias; transposed store ----
        {
            int rr = tid >> 5, o = tid & 31;
            float s = fb[o]
                    + part[(0 * 16 + rr) * 32 + o]
                    + part[(1 * 16 + rr) * 32 + o]
                    + part[(2 * 16 + rr) * 32 + o]
                    + part[(3 * 16 + rr) * 32 + o];
            g_z[o * 16384 + b * 128 + w0 + rr] = s;
        }
        // staging of the next phase is safe: all readers of xr/cw/cb/sp
        // completed before the barrier above.
    }
}

// ---------------------------------------------------------------------------
// Kernel 2: the LSTM (frozen at R7 best). Block = (f, 32-batch chunk),
// 256 threads (8 warps); warp <-> 4 cells; lane = hidden index.
// ---------------------------------------------------------------------------
__global__ __launch_bounds__(256, 1) void k_lstm(
    const float* __restrict__ w_ih0, const float* __restrict__ w_ih1,
    const float* __restrict__ w_hh,  const float* __restrict__ b_lstm)
{
    extern __shared__ ull sm2[];
    ulonglong2* W0q = (ulonglong2*)sm2;            // [8 hp2][128 g]   16KB
    ulonglong2* Wcq = (ulonglong2*)(sm2 + 2048);   // [16 hp2][128 g]  32KB
    ull*   hcat = sm2 + 6144;                      // [32 cells][32 pairs] 8KB
    float* zb   = (float*)(sm2 + 7168);            // [32 b][128 t]    16KB
    float* wi0  = zb + 4096;                       // 128
    float* bs0  = wi0 + 128;                       // 128
    float* bs1  = bs0 + 128;                       // 128

    const int tid = threadIdx.x;
    const int f   = blockIdx.x & 31;
    const int b0  = (blockIdx.x >> 5) * 32;

    const float* whh0 = w_hh  + (size_t)f        * 4096;  // [g][h]
    const float* whh1 = w_hh  + (size_t)(32 + f) * 4096;
    const float* wi1  = w_ih1 + (size_t)f        * 4096;

    for (int idx = tid; idx < 1024; idx += 256) {
        int hp2 = idx >> 7, gg = idx & 127;
        float4 v = *(const float4*)(whh0 + gg * 32 + 4 * hp2);
        W0q[idx] = make_ulonglong2(pk2(v.x, v.y), pk2(v.z, v.w));
    }
    for (int idx = tid; idx < 2048; idx += 256) {
        int hp2 = idx >> 7, gg = idx & 127;
        float4 v = (hp2 < 8) ? *(const float4*)(wi1  + gg * 32 + 4 * hp2)
                             : *(const float4*)(whh1 + gg * 32 + 4 * (hp2 - 8));
        Wcq[idx] = make_ulonglong2(pk2(v.x, v.y), pk2(v.z, v.w));
    }
    if (tid < 128) {
        wi0[tid] = w_ih0[f * 128 + tid];
        bs0[tid] = b_lstm[f * 128 + tid];
        bs1[tid] = b_lstm[(32 + f) * 128 + tid];
    }
    for (int idx = tid; idx < 4096; idx += 256)
        zb[idx] = g_z[f * 16384 + b0 * 128 + idx];
    for (int idx = tid; idx < 1024; idx += 256) hcat[idx] = 0ull;
    __syncthreads();

    const int wg = tid >> 5, lane = tid & 31;
    ull* hbase = hcat + (wg * 4) * 32;             // 4 cells x 32 pairs

    float wi0g[4], bs0g[4], bs1g[4];
    #pragma unroll
    for (int gg = 0; gg < 4; ++gg) {
        wi0g[gg] = wi0[lane + 32 * gg];
        bs0g[gg] = bs0[lane + 32 * gg];
        bs1g[gg] = bs1[lane + 32 * gg];
    }

    // layer0 weights for gate groups 0,1 held in registers (loop-invariant)
    ulonglong2 V0[8], V1[8];
    #pragma unroll
    for (int hp2 = 0; hp2 < 8; ++hp2) {
        V0[hp2] = W0q[hp2 * 128 + lane];
        V1[hp2] = W0q[hp2 * 128 + lane + 32];
    }

    float c0[4] = {0, 0, 0, 0};
    float c1[4] = {0, 0, 0, 0};
    float h1v[4];
    const float* zw = zb + (wg * 4) * 128;

    // prologue: gates0(t=0) = x(0)*wi0 + b0  (h0(-1)=0)
    ull a0[4][4];
    #pragma unroll
    for (int r = 0; r < 4; ++r) {
        float xv = zw[r * 128];
        #pragma unroll
        for (int gg = 0; gg < 4; ++gg)
            a0[r][gg] = pk2(fmaf(xv, wi0g[gg], bs0g[gg]), 0.0f);
    }

    #pragma unroll 2
    for (int t = 0; t < 128; ++t) {
        // ---- (1) a1 partial: bias + contraction over h1(t-1) (hp2 8..15) ----
        ull a1[4][4];
        #pragma unroll
        for (int r = 0; r < 4; ++r)
            #pragma unroll
            for (int gg = 0; gg < 4; ++gg)
                a1[r][gg] = pk2(bs1g[gg], 0.0f);
        #pragma unroll
        for (int hp2 = 8; hp2 < 16; ++hp2) {
            ulonglong2 u0 = Wcq[hp2 * 128 + lane];
            ulonglong2 u1 = Wcq[hp2 * 128 + lane + 32];
            ulonglong2 u2 = Wcq[hp2 * 128 + lane + 64];
            ulonglong2 u3 = Wcq[hp2 * 128 + lane + 96];
            #pragma unroll
            for (int r = 0; r < 4; ++r) {
                ulonglong2 hv = ((const ulonglong2*)(hbase + r * 32))[hp2];
                ffma2(a1[r][0], hv.x, u0.x); ffma2(a1[r][0], hv.y, u0.y);
                ffma2(a1[r][1], hv.x, u1.x); ffma2(a1[r][1], hv.y, u1.y);
                ffma2(a1[r][2], hv.x, u2.x); ffma2(a1[r][2], hv.y, u2.y);
                ffma2(a1[r][3], hv.x, u3.x); ffma2(a1[r][3], hv.y, u3.y);
            }
        }

        // ---- (2) A0: h0(t) from a0 ----
        #pragma unroll
        for (int r = 0; r < 4; ++r) {
            float gi  = redu(a0[r][0]);
            float gf  = redu(a0[r][1]);
            float gg_ = redu(a0[r][2]);
            float go  = redu(a0[r][3]);
            c0[r] = sigmf(gf) * c0[r] + sigmf(gi) * tanhfa(gg_);
            ((float*)(hbase + r * 32))[lane] = sigmf(go) * tanhfa(c0[r]);
        }
        __syncwarp();

        // ---- (3) shared-h0 GEMM: finish a1, start a0(t+1) ----
        {
            const int tn = (t + 1) & 127;
            #pragma unroll
            for (int r = 0; r < 4; ++r) {
                float xv = zw[r * 128 + tn];
                #pragma unroll
                for (int gg = 0; gg < 4; ++gg)
                    a0[r][gg] = pk2(fmaf(xv, wi0g[gg], bs0g[gg]), 0.0f);
            }
        }
        #pragma unroll
        for (int hp2 = 0; hp2 < 8; ++hp2) {
            ulonglong2 u0 = Wcq[hp2 * 128 + lane];
            ulonglong2 u1 = Wcq[hp2 * 128 + lane + 32];
            ulonglong2 u2 = Wcq[hp2 * 128 + lane + 64];
            ulonglong2 u3 = Wcq[hp2 * 128 + lane + 96];
            ulonglong2 v2 = W0q[hp2 * 128 + lane + 64];
            ulonglong2 v3 = W0q[hp2 * 128 + lane + 96];
            #pragma unroll
            for (int r = 0; r < 4; ++r) {
                ulonglong2 hv = ((const ulonglong2*)(hbase + r * 32))[hp2];
                ffma2(a1[r][0], hv.x, u0.x); ffma2(a1[r][0], hv.y, u0.y);
                ffma2(a1[r][1], hv.x, u1.x); ffma2(a1[r][1], hv.y, u1.y);
                ffma2(a1[r][2], hv.x, u2.x); ffma2(a1[r][2], hv.y, u2.y);
                ffma2(a1[r][3], hv.x, u3.x); ffma2(a1[r][3], hv.y, u3.y);
                ffma2(a0[r][0], hv.x, V0[hp2].x); ffma2(a0[r][0], hv.y, V0[hp2].y);
                ffma2(a0[r][1], hv.x, V1[hp2].x); ffma2(a0[r][1], hv.y, V1[hp2].y);
                ffma2(a0[r][2], hv.x, v2.x); ffma2(a0[r][2], hv.y, v2.y);
                ffma2(a0[r][3], hv.x, v3.x); ffma2(a0[r][3], hv.y, v3.y);
            }
        }

        // ---- (4) A1: h1(t) from a1 ----
        #pragma unroll
        for (int r = 0; r < 4; ++r) {
            float gi  = redu(a1[r][0]);
            float gf  = redu(a1[r][1]);
            float gg_ = redu(a1[r][2]);
            float go  = redu(a1[r][3]);
            c1[r]  = sigmf(gf) * c1[r] + sigmf(gi) * tanhfa(gg_);
            h1v[r] = sigmf(go) * tanhfa(c1[r]);
            ((float*)(hbase + r * 32))[32 + lane] = h1v[r];
        }
        __syncwarp();
    }

    #pragma unroll
    for (int r = 0; r < 4; ++r)
        g_comb[(size_t)(b0 + wg * 4 + r) * 1024 + f * 32 + lane] = h1v[r];
}

// ---------------------------------------------------------------------------
// Kernel 3: gaussian head. Block per b, 256 threads, float4 loads.
// ---------------------------------------------------------------------------
__global__ __launch_bounds__(256) void k_head(
    const float* __restrict__ mu_w, const float* __restrict__ mu_b,
    const float* __restrict__ lv_w, const float* __restrict__ lv_b,
    float* __restrict__ out)
{
    __shared__ float smu[8], slv[8];
    const int tid = threadIdx.x, b = blockIdx.x;

    float4 v  = ((const float4*)(g_comb + (size_t)b * 1024))[tid];
    float4 mw = ((const float4*)mu_w)[tid];
    float4 lw = ((const float4*)lv_w)[tid];
    float am = v.x * mw.x + v.y * mw.y + v.z * mw.z + v.w * mw.w;
    float al = v.x * lw.x + v.y * lw.y + v.z * lw.z + v.w * lw.w;

    #pragma unroll
    for (int s = 16; s > 0; s >>= 1) {
        am += __shfl_xor_sync(0xffffffffu, am, s);
        al += __shfl_xor_sync(0xffffffffu, al, s);
    }
    const int wg = tid >> 5, lane = tid & 31;
    if (lane == 0) { smu[wg] = am; slv[wg] = al; }
    __syncthreads();
    if (tid == 0) {
        float mu = mu_b[0], lv = lv_b[0];
        #pragma unroll
        for (int i = 0; i < 8; ++i) { mu += smu[i]; lv += slv[i]; }
        float sg = expf(0.5f * lv);
        out[b]       = mu - 1.96f * sg;
        out[128 + b] = mu;
        out[256 + b] = mu + 1.96f * sg;
        out[384 + b] = lv;
    }
}

// ---------------------------------------------------------------------------
extern "C" void kernel_launch(void* const* d_in, const int* in_sizes, int n_in,
                              void* d_out, int out_size)
{
    const float* x      = (const float*)d_in[0];
    const float* conv_w = (const float*)d_in[1];
    const float* conv_b = (const float*)d_in[2];
    const float* fc1_w  = (const float*)d_in[3];
    const float* fc1_b  = (const float*)d_in[4];
    const float* w_ih0  = (const float*)d_in[5];
    const float* w_ih1  = (const float*)d_in[6];
    const float* w_hh   = (const float*)d_in[7];
    const float* b_lstm = (const float*)d_in[8];
    const float* mu_w   = (const float*)d_in[9];
    const float* mu_b   = (const float*)d_in[10];
    const float* lv_w   = (const float*)d_in[11];
    const float* lv_b   = (const float*)d_in[12];
    float* out = (float*)d_out;

    const int SM_CF   = (33408 + 16704 + 2048 + 2112 + 768 + 256 + 32)
                        * (int)sizeof(float);                              // 221,312 B
    const int SM_LSTM = 9408 * (int)sizeof(ull);                           //  75,264 B

    cudaFuncSetAttribute(k_convfc, cudaFuncAttributeMaxDynamicSharedMemorySize, SM_CF);
    cudaFuncSetAttribute(k_lstm,   cudaFuncAttributeMaxDynamicSharedMemorySize, SM_LSTM);

    k_convfc<<<128, 512, SM_CF>>>(x, conv_w, conv_b, fc1_w, fc1_b);
    k_lstm<<<128, 256, SM_LSTM>>>(w_ih0, w_ih1, w_hh, b_lstm);
    k_head<<<128, 256>>>(mu_w, mu_b, lv_w, lv_b, out);
}

// round 10
// speedup vs baseline: 1.4967x; 1.0133x over previous
#include <cuda_runtime.h>

// ---------------------------------------------------------------------------
// Groupwise CNN + 32 independent 2-layer LSTMs + gaussian head
// ---------------------------------------------------------------------------

typedef unsigned long long ull;

#define B_    128
#define W_    128
#define FC1_  32
#define H_    32

// scratch (allocation-free rule: __device__ globals)
__device__ float g_z[FC1_ * 16384];          // [f][b*128+t]  (transposed for lstm)
__device__ float g_comb[B_ * FC1_ * H_];     // [b][f*32+h]

__device__ __forceinline__ void ffma2(ull &d, ull a, ull b) {
    asm("fma.rn.f32x2 %0, %1, %2, %0;" : "+l"(d) : "l"(a), "l"(b));
}
__device__ __forceinline__ float redu(ull a) {
    float lo, hi;
    asm("mov.b64 {%0,%1}, %2;" : "=f"(lo), "=f"(hi) : "l"(a));
    return lo + hi;
}
__device__ __forceinline__ ull pk2(float lo, float hi) {
    ull r;
    asm("mov.b64 %0, {%1,%2};" : "=l"(r) : "f"(lo), "f"(hi));
    return r;
}
__device__ __forceinline__ float sigmf(float x) {
    return __fdividef(1.0f, 1.0f + __expf(-x));
}
__device__ __forceinline__ float tanhfa(float x) {
    return __fdividef(2.0f, 1.0f + __expf(-2.0f * x)) - 1.0f;
}

// ---------------------------------------------------------------------------
// Kernel 1: FUSED conv -> relu -> maxpool -> fc1 GEMM, WARP-SPECIALIZED.
// One block per batch b, 512 threads. 16 tiles of 8 w-rows, double-buffered
// pooled tile. Warps 8-15 (producers): stage x + conv tile p. Warps 0-7
// (consumers): fc1 GEMM + combine of tile p-1. One __syncthreads per tile,
// plus one intra-group named barrier each side.
// GEMM: warp = (K-chunk cch of 4, row-group g of 2): lane=output, 4 rows/thr.
// Output TRANSPOSED: g_z[f][b*128+t].
// ---------------------------------------------------------------------------
__global__ __launch_bounds__(512) void k_convfc(
    const float* __restrict__ x,
    const float* __restrict__ conv_w, const float* __restrict__ conv_b,
    const float* __restrict__ fc1_w,  const float* __restrict__ fc1_b)
{
    extern __shared__ float smf[];
    float* Wfp  = smf;                // 32 x 1044 = 33408
    float* sp   = Wfp + 33408;        // 2 bufs x 8 rows x 1044 = 16704
    float* part = sp + 16704;         // 4c x 8r x 32o = 1024
    float* xr   = part + 1024;        // 8 x 132 = 1056
    float* cw   = xr + 1056;          // 384
    float* cb   = cw + 384;           // 128
    float* fb   = cb + 128;           // 32
    // total 52736 floats = 210,944 B

    const int tid = threadIdx.x;
    const int b   = blockIdx.x;

    // load fc1 weights (padded rows, stride 1044 = conflict-free LDS.128) + bias
    for (int o = 0; o < 32; ++o)
        for (int c = tid; c < 1040; c += 512)
            Wfp[o * 1044 + c] = fc1_w[o * 1040 + c];
    if (tid < 32) fb[tid] = fc1_b[tid];
    __syncthreads();

    if (tid >= 256) {
        // ---------------- PRODUCER: stage + conv tile p ----------------
        const int ptid = tid - 256;
        const int crow = ptid >> 5;         // 0..7
        const int ck   = (ptid >> 1) & 15;  // 0..15
        const int chal = ptid & 1;
        const int srow = ptid >> 5;         // staging row 0..7
        const int sc4  = (ptid & 31) * 4;   // staging col

        for (int p = 0; p <= 16; ++p) {
            if (p < 16) {
                const int w0 = p * 8;
                float* spb = sp + (p & 1) * 8352;

                // stage x rows (1 float4 per thread, scattered scalar STS)
                {
                    float4 v = *(const float4*)(x + (size_t)b * 16384
                                                + (w0 + srow) * 128 + sc4);
                    float* xd = xr + srow * 132 + 1 + sc4;
                    xd[0] = v.x; xd[1] = v.y; xd[2] = v.z; xd[3] = v.w;
                }
                if (ptid < 8) { xr[ptid * 132] = 0.0f; xr[ptid * 132 + 129] = 0.0f; }
                for (int i = ptid; i < 384; i += 256) cw[i] = conv_w[w0 * 48 + i];
                if (ptid < 128) cb[ptid] = conv_b[w0 * 16 + ptid];
                asm volatile("bar.sync 1, 256;" ::: "memory");

                // conv + relu + maxpool into spb (weights in regs, no divisions)
                {
                    const float c0w = cw[crow * 48 + ck * 3];
                    const float c1w = cw[crow * 48 + ck * 3 + 1];
                    const float c2w = cw[crow * 48 + ck * 3 + 2];
                    const float bb  = cb[crow * 16 + ck];
                    const float* xp = xr + crow * 132;
                    float* pp = spb + crow * 1044 + ck * 65;
                    const int j0 = chal ? 33 : 0;
                    const int j1 = chal ? 65 : 33;
                    for (int j = j0; j < j1; ++j) {
                        int pq = 2 * j;
                        float va = -1e30f, vb = -1e30f;
                        if (pq > 0)
                            va = fmaxf(0.0f, bb + c0w * xp[pq - 1] + c1w * xp[pq]
                                                 + c2w * xp[pq + 1]);
                        if (pq < 128)
                            vb = fmaxf(0.0f, bb + c0w * xp[pq]     + c1w * xp[pq + 1]
                                                 + c2w * xp[pq + 2]);
                        pp[j] = fmaxf(va, vb);
                    }
                }
            }
            __syncthreads();
        }
    } else {
        // ---------------- CONSUMER: GEMM + combine tile p-1 ----------------
        const int wid  = tid >> 5, lane = tid & 31;
        const int cch  = wid >> 1;          // K-chunk 0..3 (65 quads)
        const int g    = wid & 1;           // row-group 0..1 (4 rows)
        const int qb   = cch * 65;
        const int rr   = tid >> 5;          // combine: row 0..7
        const int oo   = tid & 31;          // combine: output

        for (int p = 0; p <= 16; ++p) {
            if (p >= 1) {
                const int w0 = (p - 1) * 8;
                const float* spb = sp + ((p - 1) & 1) * 8352;

                // GEMM over K-chunk: 4 rows per thread
                {
                    const ulonglong2* wrow = (const ulonglong2*)(Wfp + lane * 1044) + qb;
                    ull acc[4] = {0, 0, 0, 0};
                    #pragma unroll 5
                    for (int q = 0; q < 65; ++q) {
                        ulonglong2 wv = wrow[q];
                        #pragma unroll
                        for (int r = 0; r < 4; ++r) {
                            ulonglong2 hv =
                                ((const ulonglong2*)(spb + (g * 4 + r) * 1044))[qb + q];
                            ffma2(acc[r], hv.x, wv.x);
                            ffma2(acc[r], hv.y, wv.y);
                        }
                    }
                    #pragma unroll
                    for (int r = 0; r < 4; ++r)
                        part[(cch * 8 + g * 4 + r) * 32 + lane] = redu(acc[r]);
                }
                asm volatile("bar.sync 2, 256;" ::: "memory");

                // combine partials + bias; transposed store
                {
                    float s = fb[oo]
                            + part[(0 * 8 + rr) * 32 + oo]
                            + part[(1 * 8 + rr) * 32 + oo]
                            + part[(2 * 8 + rr) * 32 + oo]
                            + part[(3 * 8 + rr) * 32 + oo];
                    g_z[oo * 16384 + b * 128 + w0 + rr] = s;
                }
            }
            __syncthreads();
        }
    }
}

// ---------------------------------------------------------------------------
// Kernel 2: the LSTM (frozen at R7/R9 best). Block = (f, 32-batch chunk),
// 256 threads (8 warps); warp <-> 4 cells; lane = hidden index.
// ---------------------------------------------------------------------------
__global__ __launch_bounds__(256, 1) void k_lstm(
    const float* __restrict__ w_ih0, const float* __restrict__ w_ih1,
    const float* __restrict__ w_hh,  const float* __restrict__ b_lstm)
{
    extern __shared__ ull sm2[];
    ulonglong2* W0q = (ulonglong2*)sm2;            // [8 hp2][128 g]   16KB
    ulonglong2* Wcq = (ulonglong2*)(sm2 + 2048);   // [16 hp2][128 g]  32KB
    ull*   hcat = sm2 + 6144;                      // [32 cells][32 pairs] 8KB
    float* zb   = (float*)(sm2 + 7168);            // [32 b][128 t]    16KB
    float* wi0  = zb + 4096;                       // 128
    float* bs0  = wi0 + 128;                       // 128
    float* bs1  = bs0 + 128;                       // 128

    const int tid = threadIdx.x;
    const int f   = blockIdx.x & 31;
    const int b0  = (blockIdx.x >> 5) * 32;

    const float* whh0 = w_hh  + (size_t)f        * 4096;  // [g][h]
    const float* whh1 = w_hh  + (size_t)(32 + f) * 4096;
    const float* wi1  = w_ih1 + (size_t)f        * 4096;

    for (int idx = tid; idx < 1024; idx += 256) {
        int hp2 = idx >> 7, gg = idx & 127;
        float4 v = *(const float4*)(whh0 + gg * 32 + 4 * hp2);
        W0q[idx] = make_ulonglong2(pk2(v.x, v.y), pk2(v.z, v.w));
    }
    for (int idx = tid; idx < 2048; idx += 256) {
        int hp2 = idx >> 7, gg = idx & 127;
        float4 v = (hp2 < 8) ? *(const float4*)(wi1  + gg * 32 + 4 * hp2)
                             : *(const float4*)(whh1 + gg * 32 + 4 * (hp2 - 8));
        Wcq[idx] = make_ulonglong2(pk2(v.x, v.y), pk2(v.z, v.w));
    }
    if (tid < 128) {
        wi0[tid] = w_ih0[f * 128 + tid];
        bs0[tid] = b_lstm[f * 128 + tid];
        bs1[tid] = b_lstm[(32 + f) * 128 + tid];
    }
    for (int idx = tid; idx < 4096; idx += 256)
        zb[idx] = g_z[f * 16384 + b0 * 128 + idx];
    for (int idx = tid; idx < 1024; idx += 256) hcat[idx] = 0ull;
    __syncthreads();

    const int wg = tid >> 5, lane = tid & 31;
    ull* hbase = hcat + (wg * 4) * 32;             // 4 cells x 32 pairs

    float wi0g[4], bs0g[4], bs1g[4];
    #pragma unroll
    for (int gg = 0; gg < 4; ++gg) {
        wi0g[gg] = wi0[lane + 32 * gg];
        bs0g[gg] = bs0[lane + 32 * gg];
        bs1g[gg] = bs1[lane + 32 * gg];
    }

    // layer0 weights for gate groups 0,1 held in registers (loop-invariant)
    ulonglong2 V0[8], V1[8];
    #pragma unroll
    for (int hp2 = 0; hp2 < 8; ++hp2) {
        V0[hp2] = W0q[hp2 * 128 + lane];
        V1[hp2] = W0q[hp2 * 128 + lane + 32];
    }

    float c0[4] = {0, 0, 0, 0};
    float c1[4] = {0, 0, 0, 0};
    float h1v[4];
    const float* zw = zb + (wg * 4) * 128;

    // prologue: gates0(t=0) = x(0)*wi0 + b0  (h0(-1)=0)
    ull a0[4][4];
    #pragma unroll
    for (int r = 0; r < 4; ++r) {
        float xv = zw[r * 128];
        #pragma unroll
        for (int gg = 0; gg < 4; ++gg)
            a0[r][gg] = pk2(fmaf(xv, wi0g[gg], bs0g[gg]), 0.0f);
    }

    #pragma unroll 2
    for (int t = 0; t < 128; ++t) {
        // ---- (1) a1 partial: bias + contraction over h1(t-1) (hp2 8..15) ----
        ull a1[4][4];
        #pragma unroll
        for (int r = 0; r < 4; ++r)
            #pragma unroll
            for (int gg = 0; gg < 4; ++gg)
                a1[r][gg] = pk2(bs1g[gg], 0.0f);
        #pragma unroll
        for (int hp2 = 8; hp2 < 16; ++hp2) {
            ulonglong2 u0 = Wcq[hp2 * 128 + lane];
            ulonglong2 u1 = Wcq[hp2 * 128 + lane + 32];
            ulonglong2 u2 = Wcq[hp2 * 128 + lane + 64];
            ulonglong2 u3 = Wcq[hp2 * 128 + lane + 96];
            #pragma unroll
            for (int r = 0; r < 4; ++r) {
                ulonglong2 hv = ((const ulonglong2*)(hbase + r * 32))[hp2];
                ffma2(a1[r][0], hv.x, u0.x); ffma2(a1[r][0], hv.y, u0.y);
                ffma2(a1[r][1], hv.x, u1.x); ffma2(a1[r][1], hv.y, u1.y);
                ffma2(a1[r][2], hv.x, u2.x); ffma2(a1[r][2], hv.y, u2.y);
                ffma2(a1[r][3], hv.x, u3.x); ffma2(a1[r][3], hv.y, u3.y);
            }
        }

        // ---- (2) A0: h0(t) from a0 ----
        #pragma unroll
        for (int r = 0; r < 4; ++r) {
            float gi  = redu(a0[r][0]);
            float gf  = redu(a0[r][1]);
            float gg_ = redu(a0[r][2]);
            float go  = redu(a0[r][3]);
            c0[r] = sigmf(gf) * c0[r] + sigmf(gi) * tanhfa(gg_);
            ((float*)(hbase + r * 32))[lane] = sigmf(go) * tanhfa(c0[r]);
        }
        __syncwarp();

        // ---- (3) shared-h0 GEMM: finish a1, start a0(t+1) ----
        {
            const int tn = (t + 1) & 127;
            #pragma unroll
            for (int r = 0; r < 4; ++r) {
                float xv = zw[r * 128 + tn];
                #pragma unroll
                for (int gg = 0; gg < 4; ++gg)
                    a0[r][gg] = pk2(fmaf(xv, wi0g[gg], bs0g[gg]), 0.0f);
            }
        }
        #pragma unroll
        for (int hp2 = 0; hp2 < 8; ++hp2) {
            ulonglong2 u0 = Wcq[hp2 * 128 + lane];
            ulonglong2 u1 = Wcq[hp2 * 128 + lane + 32];
            ulonglong2 u2 = Wcq[hp2 * 128 + lane + 64];
            ulonglong2 u3 = Wcq[hp2 * 128 + lane + 96];
            ulonglong2 v2 = W0q[hp2 * 128 + lane + 64];
            ulonglong2 v3 = W0q[hp2 * 128 + lane + 96];
            #pragma unroll
            for (int r = 0; r < 4; ++r) {
                ulonglong2 hv = ((const ulonglong2*)(hbase + r * 32))[hp2];
                ffma2(a1[r][0], hv.x, u0.x); ffma2(a1[r][0], hv.y, u0.y);
                ffma2(a1[r][1], hv.x, u1.x); ffma2(a1[r][1], hv.y, u1.y);
                ffma2(a1[r][2], hv.x, u2.x); ffma2(a1[r][2], hv.y, u2.y);
                ffma2(a1[r][3], hv.x, u3.x); ffma2(a1[r][3], hv.y, u3.y);
                ffma2(a0[r][0], hv.x, V0[hp2].x); ffma2(a0[r][0], hv.y, V0[hp2].y);
                ffma2(a0[r][1], hv.x, V1[hp2].x); ffma2(a0[r][1], hv.y, V1[hp2].y);
                ffma2(a0[r][2], hv.x, v2.x); ffma2(a0[r][2], hv.y, v2.y);
                ffma2(a0[r][3], hv.x, v3.x); ffma2(a0[r][3], hv.y, v3.y);
            }
        }

        // ---- (4) A1: h1(t) from a1 ----
        #pragma unroll
        for (int r = 0; r < 4; ++r) {
            float gi  = redu(a1[r][0]);
            float gf  = redu(a1[r][1]);
            float gg_ = redu(a1[r][2]);
            float go  = redu(a1[r][3]);
            c1[r]  = sigmf(gf) * c1[r] + sigmf(gi) * tanhfa(gg_);
            h1v[r] = sigmf(go) * tanhfa(c1[r]);
            ((float*)(hbase + r * 32))[32 + lane] = h1v[r];
        }
        __syncwarp();
    }

    #pragma unroll
    for (int r = 0; r < 4; ++r)
        g_comb[(size_t)(b0 + wg * 4 + r) * 1024 + f * 32 + lane] = h1v[r];
}

// ---------------------------------------------------------------------------
// Kernel 3: gaussian head. Block per b, 256 threads, float4 loads.
// ---------------------------------------------------------------------------
__global__ __launch_bounds__(256) void k_head(
    const float* __restrict__ mu_w, const float* __restrict__ mu_b,
    const float* __restrict__ lv_w, const float* __restrict__ lv_b,
    float* __restrict__ out)
{
    __shared__ float smu[8], slv[8];
    const int tid = threadIdx.x, b = blockIdx.x;

    float4 v  = ((const float4*)(g_comb + (size_t)b * 1024))[tid];
    float4 mw = ((const float4*)mu_w)[tid];
    float4 lw = ((const float4*)lv_w)[tid];
    float am = v.x * mw.x + v.y * mw.y + v.z * mw.z + v.w * mw.w;
    float al = v.x * lw.x + v.y * lw.y + v.z * lw.z + v.w * lw.w;

    #pragma unroll
    for (int s = 16; s > 0; s >>= 1) {
        am += __shfl_xor_sync(0xffffffffu, am, s);
        al += __shfl_xor_sync(0xffffffffu, al, s);
    }
    const int wg = tid >> 5, lane = tid & 31;
    if (lane == 0) { smu[wg] = am; slv[wg] = al; }
    __syncthreads();
    if (tid == 0) {
        float mu = mu_b[0], lv = lv_b[0];
        #pragma unroll
        for (int i = 0; i < 8; ++i) { mu += smu[i]; lv += slv[i]; }
        float sg = expf(0.5f * lv);
        out[b]       = mu - 1.96f * sg;
        out[128 + b] = mu;
        out[256 + b] = mu + 1.96f * sg;
        out[384 + b] = lv;
    }
}

// ---------------------------------------------------------------------------
extern "C" void kernel_launch(void* const* d_in, const int* in_sizes, int n_in,
                              void* d_out, int out_size)
{
    const float* x      = (const float*)d_in[0];
    const float* conv_w = (const float*)d_in[1];
    const float* conv_b = (const float*)d_in[2];
    const float* fc1_w  = (const float*)d_in[3];
    const float* fc1_b  = (const float*)d_in[4];
    const float* w_ih0  = (const float*)d_in[5];
    const float* w_ih1  = (const float*)d_in[6];
    const float* w_hh   = (const float*)d_in[7];
    const float* b_lstm = (const float*)d_in[8];
    const float* mu_w   = (const float*)d_in[9];
    const float* mu_b   = (const float*)d_in[10];
    const float* lv_w   = (const float*)d_in[11];
    const float* lv_b   = (const float*)d_in[12];
    float* out = (float*)d_out;

    const int SM_CF   = 52736 * (int)sizeof(float);                        // 210,944 B
    const int SM_LSTM = 9408 * (int)sizeof(ull);                           //  75,264 B

    cudaFuncSetAttribute(k_convfc, cudaFuncAttributeMaxDynamicSharedMemorySize, SM_CF);
    cudaFuncSetAttribute(k_lstm,   cudaFuncAttributeMaxDynamicSharedMemorySize, SM_LSTM);

    k_convfc<<<128, 512, SM_CF>>>(x, conv_w, conv_b, fc1_w, fc1_b);
    k_lstm<<<128, 256, SM_LSTM>>>(w_ih0, w_ih1, w_hh, b_lstm);
    k_head<<<128, 256>>>(mu_w, mu_b, lv_w, lv_b, out);
}

// round 11
// speedup vs baseline: 1.5451x; 1.0323x over previous
#include <cuda_runtime.h>

// ---------------------------------------------------------------------------
// Groupwise CNN + 32 independent 2-layer LSTMs + gaussian head
// ---------------------------------------------------------------------------

typedef unsigned long long ull;

#define B_    128
#define W_    128
#define FC1_  32
#define H_    32

// scratch (allocation-free rule: __device__ globals)
__device__ float g_z[FC1_ * 16384];          // [f][b*128+t]  (transposed for lstm)
__device__ float g_comb[B_ * FC1_ * H_];     // [b][f*32+h]

__device__ __forceinline__ void ffma2(ull &d, ull a, ull b) {
    asm("fma.rn.f32x2 %0, %1, %2, %0;" : "+l"(d) : "l"(a), "l"(b));
}
__device__ __forceinline__ float redu(ull a) {
    float lo, hi;
    asm("mov.b64 {%0,%1}, %2;" : "=f"(lo), "=f"(hi) : "l"(a));
    return lo + hi;
}
__device__ __forceinline__ ull pk2(float lo, float hi) {
    ull r;
    asm("mov.b64 %0, {%1,%2};" : "=l"(r) : "f"(lo), "f"(hi));
    return r;
}
__device__ __forceinline__ float sigmf(float x) {
    return __fdividef(1.0f, 1.0f + __expf(-x));
}
__device__ __forceinline__ float tanhfa(float x) {
    return __fdividef(2.0f, 1.0f + __expf(-2.0f * x)) - 1.0f;
}

// ---------------------------------------------------------------------------
// Kernel 1: FUSED conv -> relu -> maxpool -> fc1 GEMM, WARP-SPECIALIZED.
// One block per batch b, 512 threads. 16 tiles of 8 w-rows, double-buffered.
// Producers (warps 8-15): stage x + ROLLING-REGISTER conv (1 LDS.64 per j).
// Consumers (warps 0-7): FULL-ROW Q-SPLIT GEMM — each warp does all 8 rows
// over a disjoint q-chunk (33/33/33/33/32/32/32/32 quads), halving weight
// wavefronts; then combine of 8 chunk-partials + transposed store.
// ---------------------------------------------------------------------------
__global__ __launch_bounds__(512) void k_convfc(
    const float* __restrict__ x,
    const float* __restrict__ conv_w, const float* __restrict__ conv_b,
    const float* __restrict__ fc1_w,  const float* __restrict__ fc1_b)
{
    extern __shared__ float smf[];
    float* Wfp  = smf;                // 32 x 1044 = 33408
    float* sp   = Wfp + 33408;        // 2 bufs x 8 rows x 1044 = 16704
    float* part = sp + 16704;         // 8c x 8r x 32o = 2048
    float* xr   = part + 2048;        // 8 x 132 = 1056
    float* cw   = xr + 1056;          // 384
    float* cb   = cw + 384;           // 128
    float* fb   = cb + 128;           // 32
    // total 53760 floats = 215,040 B

    const int tid = threadIdx.x;
    const int b   = blockIdx.x;

    // load fc1 weights (padded rows, stride 1044 = conflict-free LDS.128) + bias
    for (int o = 0; o < 32; ++o)
        for (int c = tid; c < 1040; c += 512)
            Wfp[o * 1044 + c] = fc1_w[o * 1040 + c];
    if (tid < 32) fb[tid] = fc1_b[tid];
    __syncthreads();

    if (tid >= 256) {
        // ---------------- PRODUCER: stage + conv tile p ----------------
        const int ptid = tid - 256;
        const int crow = ptid >> 5;         // 0..7
        const int ck   = (ptid >> 1) & 15;  // 0..15
        const int chal = ptid & 1;
        const int srow = ptid >> 5;         // staging row 0..7
        const int sc4  = (ptid & 31) * 4;   // staging col

        const int j0    = chal ? 33 : 0;
        const int iters = chal ? 32 : 33;

        for (int p = 0; p <= 16; ++p) {
            if (p < 16) {
                const int w0 = p * 8;
                float* spb = sp + (p & 1) * 8352;

                // stage x rows (1 float4 per thread)
                {
                    float4 v = *(const float4*)(x + (size_t)b * 16384
                                                + (w0 + srow) * 128 + sc4);
                    float* xd = xr + srow * 132 + 1 + sc4;
                    xd[0] = v.x; xd[1] = v.y; xd[2] = v.z; xd[3] = v.w;
                }
                if (ptid < 8) { xr[ptid * 132] = 0.0f; xr[ptid * 132 + 129] = 0.0f; }
                for (int i = ptid; i < 384; i += 256) cw[i] = conv_w[w0 * 48 + i];
                if (ptid < 128) cb[ptid] = conv_b[w0 * 16 + ptid];
                asm volatile("bar.sync 1, 256;" ::: "memory");

                // conv + relu + maxpool: rolling-register window, 1 LDS.64/j
                {
                    const float c0w = cw[crow * 48 + ck * 3];
                    const float c1w = cw[crow * 48 + ck * 3 + 1];
                    const float c2w = cw[crow * 48 + ck * 3 + 2];
                    const float bb  = cb[crow * 16 + ck];
                    const float* xp = xr + crow * 132;
                    float* pp = spb + crow * 1044 + ck * 65;

                    float2 Pj  = *(const float2*)(xp + 2 * j0);     // {xp[2j0], xp[2j0+1]}
                    float  pm1 = chal ? xp[2 * j0 - 1] : 0.0f;      // xp[p-1] (unused at j=0)
                    for (int it = 0; it < iters; ++it) {
                        const int j = j0 + it;
                        const int pq = 2 * j;
                        float2 Pn = *(const float2*)(xp + pq + 2);  // {xp[p+2], xp[p+3]}
                        float va = -1e30f, vb = -1e30f;
                        if (pq > 0)
                            va = fmaxf(0.0f, bb + c0w * pm1 + c1w * Pj.x + c2w * Pj.y);
                        if (pq < 128)
                            vb = fmaxf(0.0f, bb + c0w * Pj.x + c1w * Pj.y + c2w * Pn.x);
                        pp[j] = fmaxf(va, vb);
                        pm1 = Pj.y;
                        Pj  = Pn;
                    }
                }
            }
            __syncthreads();
        }
    } else {
        // ---------------- CONSUMER: GEMM + combine tile p-1 ----------------
        const int wid  = tid >> 5, lane = tid & 31;
        const int qn   = (wid < 4) ? 33 : 32;                    // quads this warp
        const int qb   = (wid < 4) ? wid * 33 : 132 + (wid - 4) * 32;
        const int rr   = tid >> 5;          // combine: row 0..7
        const int oo   = tid & 31;          // combine: output

        for (int p = 0; p <= 16; ++p) {
            if (p >= 1) {
                const int w0 = (p - 1) * 8;
                const float* spb = sp + ((p - 1) & 1) * 8352;

                // GEMM: all 8 rows over this warp's q-chunk
                {
                    const ulonglong2* wrow = (const ulonglong2*)(Wfp + lane * 1044) + qb;
                    ull acc[8] = {0, 0, 0, 0, 0, 0, 0, 0};
                    #pragma unroll 3
                    for (int q = 0; q < qn; ++q) {
                        ulonglong2 wv = wrow[q];
                        #pragma unroll
                        for (int r = 0; r < 8; ++r) {
                            ulonglong2 hv =
                                ((const ulonglong2*)(spb + r * 1044))[qb + q];
                            ffma2(acc[r], hv.x, wv.x);
                            ffma2(acc[r], hv.y, wv.y);
                        }
                    }
                    #pragma unroll
                    for (int r = 0; r < 8; ++r)
                        part[(wid * 8 + r) * 32 + lane] = redu(acc[r]);
                }
                asm volatile("bar.sync 2, 256;" ::: "memory");

                // combine 8 chunk-partials + bias; transposed store
                {
                    float s = fb[oo];
                    #pragma unroll
                    for (int c = 0; c < 8; ++c)
                        s += part[(c * 8 + rr) * 32 + oo];
                    g_z[oo * 16384 + b * 128 + w0 + rr] = s;
                }
            }
            __syncthreads();
        }
    }
}

// ---------------------------------------------------------------------------
// Kernel 2: the LSTM (frozen at R7/R9 best). Block = (f, 32-batch chunk),
// 256 threads (8 warps); warp <-> 4 cells; lane = hidden index.
// ---------------------------------------------------------------------------
__global__ __launch_bounds__(256, 1) void k_lstm(
    const float* __restrict__ w_ih0, const float* __restrict__ w_ih1,
    const float* __restrict__ w_hh,  const float* __restrict__ b_lstm)
{
    extern __shared__ ull sm2[];
    ulonglong2* W0q = (ulonglong2*)sm2;            // [8 hp2][128 g]   16KB
    ulonglong2* Wcq = (ulonglong2*)(sm2 + 2048);   // [16 hp2][128 g]  32KB
    ull*   hcat = sm2 + 6144;                      // [32 cells][32 pairs] 8KB
    float* zb   = (float*)(sm2 + 7168);            // [32 b][128 t]    16KB
    float* wi0  = zb + 4096;                       // 128
    float* bs0  = wi0 + 128;                       // 128
    float* bs1  = bs0 + 128;                       // 128

    const int tid = threadIdx.x;
    const int f   = blockIdx.x & 31;
    const int b0  = (blockIdx.x >> 5) * 32;

    const float* whh0 = w_hh  + (size_t)f        * 4096;  // [g][h]
    const float* whh1 = w_hh  + (size_t)(32 + f) * 4096;
    const float* wi1  = w_ih1 + (size_t)f        * 4096;

    for (int idx = tid; idx < 1024; idx += 256) {
        int hp2 = idx >> 7, gg = idx & 127;
        float4 v = *(const float4*)(whh0 + gg * 32 + 4 * hp2);
        W0q[idx] = make_ulonglong2(pk2(v.x, v.y), pk2(v.z, v.w));
    }
    for (int idx = tid; idx < 2048; idx += 256) {
        int hp2 = idx >> 7, gg = idx & 127;
        float4 v = (hp2 < 8) ? *(const float4*)(wi1  + gg * 32 + 4 * hp2)
                             : *(const float4*)(whh1 + gg * 32 + 4 * (hp2 - 8));
        Wcq[idx] = make_ulonglong2(pk2(v.x, v.y), pk2(v.z, v.w));
    }
    if (tid < 128) {
        wi0[tid] = w_ih0[f * 128 + tid];
        bs0[tid] = b_lstm[f * 128 + tid];
        bs1[tid] = b_lstm[(32 + f) * 128 + tid];
    }
    for (int idx = tid; idx < 4096; idx += 256)
        zb[idx] = g_z[f * 16384 + b0 * 128 + idx];
    for (int idx = tid; idx < 1024; idx += 256) hcat[idx] = 0ull;
    __syncthreads();

    const int wg = tid >> 5, lane = tid & 31;
    ull* hbase = hcat + (wg * 4) * 32;             // 4 cells x 32 pairs

    float wi0g[4], bs0g[4], bs1g[4];
    #pragma unroll
    for (int gg = 0; gg < 4; ++gg) {
        wi0g[gg] = wi0[lane + 32 * gg];
        bs0g[gg] = bs0[lane + 32 * gg];
        bs1g[gg] = bs1[lane + 32 * gg];
    }

    // layer0 weights for gate groups 0,1 held in registers (loop-invariant)
    ulonglong2 V0[8], V1[8];
    #pragma unroll
    for (int hp2 = 0; hp2 < 8; ++hp2) {
        V0[hp2] = W0q[hp2 * 128 + lane];
        V1[hp2] = W0q[hp2 * 128 + lane + 32];
    }

    float c0[4] = {0, 0, 0, 0};
    float c1[4] = {0, 0, 0, 0};
    float h1v[4];
    const float* zw = zb + (wg * 4) * 128;

    // prologue: gates0(t=0) = x(0)*wi0 + b0  (h0(-1)=0)
    ull a0[4][4];
    #pragma unroll
    for (int r = 0; r < 4; ++r) {
        float xv = zw[r * 128];
        #pragma unroll
        for (int gg = 0; gg < 4; ++gg)
            a0[r][gg] = pk2(fmaf(xv, wi0g[gg], bs0g[gg]), 0.0f);
    }

    #pragma unroll 2
    for (int t = 0; t < 128; ++t) {
        // ---- (1) a1 partial: bias + contraction over h1(t-1) (hp2 8..15) ----
        ull a1[4][4];
        #pragma unroll
        for (int r = 0; r < 4; ++r)
            #pragma unroll
            for (int gg = 0; gg < 4; ++gg)
                a1[r][gg] = pk2(bs1g[gg], 0.0f);
        #pragma unroll
        for (int hp2 = 8; hp2 < 16; ++hp2) {
            ulonglong2 u0 = Wcq[hp2 * 128 + lane];
            ulonglong2 u1 = Wcq[hp2 * 128 + lane + 32];
            ulonglong2 u2 = Wcq[hp2 * 128 + lane + 64];
            ulonglong2 u3 = Wcq[hp2 * 128 + lane + 96];
            #pragma unroll
            for (int r = 0; r < 4; ++r) {
                ulonglong2 hv = ((const ulonglong2*)(hbase + r * 32))[hp2];
                ffma2(a1[r][0], hv.x, u0.x); ffma2(a1[r][0], hv.y, u0.y);
                ffma2(a1[r][1], hv.x, u1.x); ffma2(a1[r][1], hv.y, u1.y);
                ffma2(a1[r][2], hv.x, u2.x); ffma2(a1[r][2], hv.y, u2.y);
                ffma2(a1[r][3], hv.x, u3.x); ffma2(a1[r][3], hv.y, u3.y);
            }
        }

        // ---- (2) A0: h0(t) from a0 ----
        #pragma unroll
        for (int r = 0; r < 4; ++r) {
            float gi  = redu(a0[r][0]);
            float gf  = redu(a0[r][1]);
            float gg_ = redu(a0[r][2]);
            float go  = redu(a0[r][3]);
            c0[r] = sigmf(gf) * c0[r] + sigmf(gi) * tanhfa(gg_);
            ((float*)(hbase + r * 32))[lane] = sigmf(go) * tanhfa(c0[r]);
        }
        __syncwarp();

        // ---- (3) shared-h0 GEMM: finish a1, start a0(t+1) ----
        {
            const int tn = (t + 1) & 127;
            #pragma unroll
            for (int r = 0; r < 4; ++r) {
                float xv = zw[r * 128 + tn];
                #pragma unroll
                for (int gg = 0; gg < 4; ++gg)
                    a0[r][gg] = pk2(fmaf(xv, wi0g[gg], bs0g[gg]), 0.0f);
            }
        }
        #pragma unroll
        for (int hp2 = 0; hp2 < 8; ++hp2) {
            ulonglong2 u0 = Wcq[hp2 * 128 + lane];
            ulonglong2 u1 = Wcq[hp2 * 128 + lane + 32];
            ulonglong2 u2 = Wcq[hp2 * 128 + lane + 64];
            ulonglong2 u3 = Wcq[hp2 * 128 + lane + 96];
            ulonglong2 v2 = W0q[hp2 * 128 + lane + 64];
            ulonglong2 v3 = W0q[hp2 * 128 + lane + 96];
            #pragma unroll
            for (int r = 0; r < 4; ++r) {
                ulonglong2 hv = ((const ulonglong2*)(hbase + r * 32))[hp2];
                ffma2(a1[r][0], hv.x, u0.x); ffma2(a1[r][0], hv.y, u0.y);
                ffma2(a1[r][1], hv.x, u1.x); ffma2(a1[r][1], hv.y, u1.y);
                ffma2(a1[r][2], hv.x, u2.x); ffma2(a1[r][2], hv.y, u2.y);
                ffma2(a1[r][3], hv.x, u3.x); ffma2(a1[r][3], hv.y, u3.y);
                ffma2(a0[r][0], hv.x, V0[hp2].x); ffma2(a0[r][0], hv.y, V0[hp2].y);
                ffma2(a0[r][1], hv.x, V1[hp2].x); ffma2(a0[r][1], hv.y, V1[hp2].y);
                ffma2(a0[r][2], hv.x, v2.x); ffma2(a0[r][2], hv.y, v2.y);
                ffma2(a0[r][3], hv.x, v3.x); ffma2(a0[r][3], hv.y, v3.y);
            }
        }

        // ---- (4) A1: h1(t) from a1 ----
        #pragma unroll
        for (int r = 0; r < 4; ++r) {
            float gi  = redu(a1[r][0]);
            float gf  = redu(a1[r][1]);
            float gg_ = redu(a1[r][2]);
            float go  = redu(a1[r][3]);
            c1[r]  = sigmf(gf) * c1[r] + sigmf(gi) * tanhfa(gg_);
            h1v[r] = sigmf(go) * tanhfa(c1[r]);
            ((float*)(hbase + r * 32))[32 + lane] = h1v[r];
        }
        __syncwarp();
    }

    #pragma unroll
    for (int r = 0; r < 4; ++r)
        g_comb[(size_t)(b0 + wg * 4 + r) * 1024 + f * 32 + lane] = h1v[r];
}

// ---------------------------------------------------------------------------
// Kernel 3: gaussian head. Block per b, 256 threads, float4 loads.
// ---------------------------------------------------------------------------
__global__ __launch_bounds__(256) void k_head(
    const float* __restrict__ mu_w, const float* __restrict__ mu_b,
    const float* __restrict__ lv_w, const float* __restrict__ lv_b,
    float* __restrict__ out)
{
    __shared__ float smu[8], slv[8];
    const int tid = threadIdx.x, b = blockIdx.x;

    float4 v  = ((const float4*)(g_comb + (size_t)b * 1024))[tid];
    float4 mw = ((const float4*)mu_w)[tid];
    float4 lw = ((const float4*)lv_w)[tid];
    float am = v.x * mw.x + v.y * mw.y + v.z * mw.z + v.w * mw.w;
    float al = v.x * lw.x + v.y * lw.y + v.z * lw.z + v.w * lw.w;

    #pragma unroll
    for (int s = 16; s > 0; s >>= 1) {
        am += __shfl_xor_sync(0xffffffffu, am, s);
        al += __shfl_xor_sync(0xffffffffu, al, s);
    }
    const int wg = tid >> 5, lane = tid & 31;
    if (lane == 0) { smu[wg] = am; slv[wg] = al; }
    __syncthreads();
    if (tid == 0) {
        float mu = mu_b[0], lv = lv_b[0];
        #pragma unroll
        for (int i = 0; i < 8; ++i) { mu += smu[i]; lv += slv[i]; }
        float sg = expf(0.5f * lv);
        out[b]       = mu - 1.96f * sg;
        out[128 + b] = mu;
        out[256 + b] = mu + 1.96f * sg;
        out[384 + b] = lv;
    }
}

// ---------------------------------------------------------------------------
extern "C" void kernel_launch(void* const* d_in, const int* in_sizes, int n_in,
                              void* d_out, int out_size)
{
    const float* x      = (const float*)d_in[0];
    const float* conv_w = (const float*)d_in[1];
    const float* conv_b = (const float*)d_in[2];
    const float* fc1_w  = (const float*)d_in[3];
    const float* fc1_b  = (const float*)d_in[4];
    const float* w_ih0  = (const float*)d_in[5];
    const float* w_ih1  = (const float*)d_in[6];
    const float* w_hh   = (const float*)d_in[7];
    const float* b_lstm = (const float*)d_in[8];
    const float* mu_w   = (const float*)d_in[9];
    const float* mu_b   = (const float*)d_in[10];
    const float* lv_w   = (const float*)d_in[11];
    const float* lv_b   = (const float*)d_in[12];
    float* out = (float*)d_out;

    const int SM_CF   = 53760 * (int)sizeof(float);                        // 215,040 B
    const int SM_LSTM = 9408 * (int)sizeof(ull);                           //  75,264 B

    cudaFuncSetAttribute(k_convfc, cudaFuncAttributeMaxDynamicSharedMemorySize, SM_CF);
    cudaFuncSetAttribute(k_lstm,   cudaFuncAttributeMaxDynamicSharedMemorySize, SM_LSTM);

    k_convfc<<<128, 512, SM_CF>>>(x, conv_w, conv_b, fc1_w, fc1_b);
    k_lstm<<<128, 256, SM_LSTM>>>(w_ih0, w_ih1, w_hh, b_lstm);
    k_head<<<128, 256>>>(mu_w, mu_b, lv_w, lv_b, out);
}

// round 12
// speedup vs baseline: 1.7433x; 1.1283x over previous
#include <cuda_runtime.h>

// ---------------------------------------------------------------------------
// Groupwise CNN + 32 independent 2-layer LSTMs + gaussian head
// ---------------------------------------------------------------------------

typedef unsigned long long ull;

#define B_    128
#define W_    128
#define FC1_  32
#define H_    32

// scratch (allocation-free rule: __device__ globals)
__device__ float g_z[FC1_ * 16384];          // [f][b*128+t]  (transposed for lstm)
__device__ float g_comb[B_ * FC1_ * H_];     // [b][f*32+h]

__device__ __forceinline__ void ffma2(ull &d, ull a, ull b) {
    asm("fma.rn.f32x2 %0, %1, %2, %0;" : "+l"(d) : "l"(a), "l"(b));
}
__device__ __forceinline__ float redu(ull a) {
    float lo, hi;
    asm("mov.b64 {%0,%1}, %2;" : "=f"(lo), "=f"(hi) : "l"(a));
    return lo + hi;
}
__device__ __forceinline__ ull pk2(float lo, float hi) {
    ull r;
    asm("mov.b64 %0, {%1,%2};" : "=l"(r) : "f"(lo), "f"(hi));
    return r;
}
// fast activations for the LSTM (single-MUFU tanh; sigmoid via exact identity)
__device__ __forceinline__ float tanha(float x) {
    float r;
    asm("tanh.approx.f32 %0, %1;" : "=f"(r) : "f"(x));
    return r;
}
__device__ __forceinline__ float sigma(float x) {
    return fmaf(tanha(0.5f * x), 0.5f, 0.5f);
}

// ---------------------------------------------------------------------------
// Kernel 1: FUSED conv -> relu -> maxpool -> fc1 GEMM, WARP-SPECIALIZED.
// (frozen at R11 best)
// ---------------------------------------------------------------------------
__global__ __launch_bounds__(512) void k_convfc(
    const float* __restrict__ x,
    const float* __restrict__ conv_w, const float* __restrict__ conv_b,
    const float* __restrict__ fc1_w,  const float* __restrict__ fc1_b)
{
    extern __shared__ float smf[];
    float* Wfp  = smf;                // 32 x 1044 = 33408
    float* sp   = Wfp + 33408;        // 2 bufs x 8 rows x 1044 = 16704
    float* part = sp + 16704;         // 8c x 8r x 32o = 2048
    float* xr   = part + 2048;        // 8 x 132 = 1056
    float* cw   = xr + 1056;          // 384
    float* cb   = cw + 384;           // 128
    float* fb   = cb + 128;           // 32
    // total 53760 floats = 215,040 B

    const int tid = threadIdx.x;
    const int b   = blockIdx.x;

    for (int o = 0; o < 32; ++o)
        for (int c = tid; c < 1040; c += 512)
            Wfp[o * 1044 + c] = fc1_w[o * 1040 + c];
    if (tid < 32) fb[tid] = fc1_b[tid];
    __syncthreads();

    if (tid >= 256) {
        // ---------------- PRODUCER: stage + conv tile p ----------------
        const int ptid = tid - 256;
        const int crow = ptid >> 5;
        const int ck   = (ptid >> 1) & 15;
        const int chal = ptid & 1;
        const int srow = ptid >> 5;
        const int sc4  = (ptid & 31) * 4;

        const int j0    = chal ? 33 : 0;
        const int iters = chal ? 32 : 33;

        for (int p = 0; p <= 16; ++p) {
            if (p < 16) {
                const int w0 = p * 8;
                float* spb = sp + (p & 1) * 8352;

                {
                    float4 v = *(const float4*)(x + (size_t)b * 16384
                                                + (w0 + srow) * 128 + sc4);
                    float* xd = xr + srow * 132 + 1 + sc4;
                    xd[0] = v.x; xd[1] = v.y; xd[2] = v.z; xd[3] = v.w;
                }
                if (ptid < 8) { xr[ptid * 132] = 0.0f; xr[ptid * 132 + 129] = 0.0f; }
                for (int i = ptid; i < 384; i += 256) cw[i] = conv_w[w0 * 48 + i];
                if (ptid < 128) cb[ptid] = conv_b[w0 * 16 + ptid];
                asm volatile("bar.sync 1, 256;" ::: "memory");

                {
                    const float c0w = cw[crow * 48 + ck * 3];
                    const float c1w = cw[crow * 48 + ck * 3 + 1];
                    const float c2w = cw[crow * 48 + ck * 3 + 2];
                    const float bb  = cb[crow * 16 + ck];
                    const float* xp = xr + crow * 132;
                    float* pp = spb + crow * 1044 + ck * 65;

                    float2 Pj  = *(const float2*)(xp + 2 * j0);
                    float  pm1 = chal ? xp[2 * j0 - 1] : 0.0f;
                    for (int it = 0; it < iters; ++it) {
                        const int j = j0 + it;
                        const int pq = 2 * j;
                        float2 Pn = *(const float2*)(xp + pq + 2);
                        float va = -1e30f, vb = -1e30f;
                        if (pq > 0)
                            va = fmaxf(0.0f, bb + c0w * pm1 + c1w * Pj.x + c2w * Pj.y);
                        if (pq < 128)
                            vb = fmaxf(0.0f, bb + c0w * Pj.x + c1w * Pj.y + c2w * Pn.x);
                        pp[j] = fmaxf(va, vb);
                        pm1 = Pj.y;
                        Pj  = Pn;
                    }
                }
            }
            __syncthreads();
        }
    } else {
        // ---------------- CONSUMER: GEMM + combine tile p-1 ----------------
        const int wid  = tid >> 5, lane = tid & 31;
        const int qn   = (wid < 4) ? 33 : 32;
        const int qb   = (wid < 4) ? wid * 33 : 132 + (wid - 4) * 32;
        const int rr   = tid >> 5;
        const int oo   = tid & 31;

        for (int p = 0; p <= 16; ++p) {
            if (p >= 1) {
                const int w0 = (p - 1) * 8;
                const float* spb = sp + ((p - 1) & 1) * 8352;

                {
                    const ulonglong2* wrow = (const ulonglong2*)(Wfp + lane * 1044) + qb;
                    ull acc[8] = {0, 0, 0, 0, 0, 0, 0, 0};
                    #pragma unroll 3
                    for (int q = 0; q < qn; ++q) {
                        ulonglong2 wv = wrow[q];
                        #pragma unroll
                        for (int r = 0; r < 8; ++r) {
                            ulonglong2 hv =
                                ((const ulonglong2*)(spb + r * 1044))[qb + q];
                            ffma2(acc[r], hv.x, wv.x);
                            ffma2(acc[r], hv.y, wv.y);
                        }
                    }
                    #pragma unroll
                    for (int r = 0; r < 8; ++r)
                        part[(wid * 8 + r) * 32 + lane] = redu(acc[r]);
                }
                asm volatile("bar.sync 2, 256;" ::: "memory");

                {
                    float s = fb[oo];
                    #pragma unroll
                    for (int c = 0; c < 8; ++c)
                        s += part[(c * 8 + rr) * 32 + oo];
                    g_z[oo * 16384 + b * 128 + w0 + rr] = s;
                }
            }
            __syncthreads();
        }
    }
}

// ---------------------------------------------------------------------------
// Kernel 2: the LSTM. Structure frozen at R7/R9 best; activations switched
// to tanh.approx (1 MUFU) with sigmoid(x) = 0.5*tanh(0.5x)+0.5.
// ---------------------------------------------------------------------------
__global__ __launch_bounds__(256, 1) void k_lstm(
    const float* __restrict__ w_ih0, const float* __restrict__ w_ih1,
    const float* __restrict__ w_hh,  const float* __restrict__ b_lstm)
{
    extern __shared__ ull sm2[];
    ulonglong2* W0q = (ulonglong2*)sm2;            // [8 hp2][128 g]   16KB
    ulonglong2* Wcq = (ulonglong2*)(sm2 + 2048);   // [16 hp2][128 g]  32KB
    ull*   hcat = sm2 + 6144;                      // [32 cells][32 pairs] 8KB
    float* zb   = (float*)(sm2 + 7168);            // [32 b][128 t]    16KB
    float* wi0  = zb + 4096;                       // 128
    float* bs0  = wi0 + 128;                       // 128
    float* bs1  = bs0 + 128;                       // 128

    const int tid = threadIdx.x;
    const int f   = blockIdx.x & 31;
    const int b0  = (blockIdx.x >> 5) * 32;

    const float* whh0 = w_hh  + (size_t)f        * 4096;  // [g][h]
    const float* whh1 = w_hh  + (size_t)(32 + f) * 4096;
    const float* wi1  = w_ih1 + (size_t)f        * 4096;

    for (int idx = tid; idx < 1024; idx += 256) {
        int hp2 = idx >> 7, gg = idx & 127;
        float4 v = *(const float4*)(whh0 + gg * 32 + 4 * hp2);
        W0q[idx] = make_ulonglong2(pk2(v.x, v.y), pk2(v.z, v.w));
    }
    for (int idx = tid; idx < 2048; idx += 256) {
        int hp2 = idx >> 7, gg = idx & 127;
        float4 v = (hp2 < 8) ? *(const float4*)(wi1  + gg * 32 + 4 * hp2)
                             : *(const float4*)(whh1 + gg * 32 + 4 * (hp2 - 8));
        Wcq[idx] = make_ulonglong2(pk2(v.x, v.y), pk2(v.z, v.w));
    }
    if (tid < 128) {
        wi0[tid] = w_ih0[f * 128 + tid];
        bs0[tid] = b_lstm[f * 128 + tid];
        bs1[tid] = b_lstm[(32 + f) * 128 + tid];
    }
    for (int idx = tid; idx < 4096; idx += 256)
        zb[idx] = g_z[f * 16384 + b0 * 128 + idx];
    for (int idx = tid; idx < 1024; idx += 256) hcat[idx] = 0ull;
    __syncthreads();

    const int wg = tid >> 5, lane = tid & 31;
    ull* hbase = hcat + (wg * 4) * 32;             // 4 cells x 32 pairs

    float wi0g[4], bs0g[4], bs1g[4];
    #pragma unroll
    for (int gg = 0; gg < 4; ++gg) {
        wi0g[gg] = wi0[lane + 32 * gg];
        bs0g[gg] = bs0[lane + 32 * gg];
        bs1g[gg] = bs1[lane + 32 * gg];
    }

    // layer0 weights for gate groups 0,1 held in registers (loop-invariant)
    ulonglong2 V0[8], V1[8];
    #pragma unroll
    for (int hp2 = 0; hp2 < 8; ++hp2) {
        V0[hp2] = W0q[hp2 * 128 + lane];
        V1[hp2] = W0q[hp2 * 128 + lane + 32];
    }

    float c0[4] = {0, 0, 0, 0};
    float c1[4] = {0, 0, 0, 0};
    float h1v[4];
    const float* zw = zb + (wg * 4) * 128;

    // prologue: gates0(t=0) = x(0)*wi0 + b0  (h0(-1)=0)
    ull a0[4][4];
    #pragma unroll
    for (int r = 0; r < 4; ++r) {
        float xv = zw[r * 128];
        #pragma unroll
        for (int gg = 0; gg < 4; ++gg)
            a0[r][gg] = pk2(fmaf(xv, wi0g[gg], bs0g[gg]), 0.0f);
    }

    #pragma unroll 2
    for (int t = 0; t < 128; ++t) {
        // ---- (1) a1 partial: bias + contraction over h1(t-1) (hp2 8..15) ----
        ull a1[4][4];
        #pragma unroll
        for (int r = 0; r < 4; ++r)
            #pragma unroll
            for (int gg = 0; gg < 4; ++gg)
                a1[r][gg] = pk2(bs1g[gg], 0.0f);
        #pragma unroll
        for (int hp2 = 8; hp2 < 16; ++hp2) {
            ulonglong2 u0 = Wcq[hp2 * 128 + lane];
            ulonglong2 u1 = Wcq[hp2 * 128 + lane + 32];
            ulonglong2 u2 = Wcq[hp2 * 128 + lane + 64];
            ulonglong2 u3 = Wcq[hp2 * 128 + lane + 96];
            #pragma unroll
            for (int r = 0; r < 4; ++r) {
                ulonglong2 hv = ((const ulonglong2*)(hbase + r * 32))[hp2];
                ffma2(a1[r][0], hv.x, u0.x); ffma2(a1[r][0], hv.y, u0.y);
                ffma2(a1[r][1], hv.x, u1.x); ffma2(a1[r][1], hv.y, u1.y);
                ffma2(a1[r][2], hv.x, u2.x); ffma2(a1[r][2], hv.y, u2.y);
                ffma2(a1[r][3], hv.x, u3.x); ffma2(a1[r][3], hv.y, u3.y);
            }
        }

        // ---- (2) A0: h0(t) from a0 ----
        #pragma unroll
        for (int r = 0; r < 4; ++r) {
            float gi  = redu(a0[r][0]);
            float gf  = redu(a0[r][1]);
            float gg_ = redu(a0[r][2]);
            float go  = redu(a0[r][3]);
            c0[r] = sigma(gf) * c0[r] + sigma(gi) * tanha(gg_);
            ((float*)(hbase + r * 32))[lane] = sigma(go) * tanha(c0[r]);
        }
        __syncwarp();

        // ---- (3) shared-h0 GEMM: finish a1, start a0(t+1) ----
        {
            const int tn = (t + 1) & 127;
            #pragma unroll
            for (int r = 0; r < 4; ++r) {
                float xv = zw[r * 128 + tn];
                #pragma unroll
                for (int gg = 0; gg < 4; ++gg)
                    a0[r][gg] = pk2(fmaf(xv, wi0g[gg], bs0g[gg]), 0.0f);
            }
        }
        #pragma unroll
        for (int hp2 = 0; hp2 < 8; ++hp2) {
            ulonglong2 u0 = Wcq[hp2 * 128 + lane];
            ulonglong2 u1 = Wcq[hp2 * 128 + lane + 32];
            ulonglong2 u2 = Wcq[hp2 * 128 + lane + 64];
            ulonglong2 u3 = Wcq[hp2 * 128 + lane + 96];
            ulonglong2 v2 = W0q[hp2 * 128 + lane + 64];
            ulonglong2 v3 = W0q[hp2 * 128 + lane + 96];
            #pragma unroll
            for (int r = 0; r < 4; ++r) {
                ulonglong2 hv = ((const ulonglong2*)(hbase + r * 32))[hp2];
                ffma2(a1[r][0], hv.x, u0.x); ffma2(a1[r][0], hv.y, u0.y);
                ffma2(a1[r][1], hv.x, u1.x); ffma2(a1[r][1], hv.y, u1.y);
                ffma2(a1[r][2], hv.x, u2.x); ffma2(a1[r][2], hv.y, u2.y);
                ffma2(a1[r][3], hv.x, u3.x); ffma2(a1[r][3], hv.y, u3.y);
                ffma2(a0[r][0], hv.x, V0[hp2].x); ffma2(a0[r][0], hv.y, V0[hp2].y);
                ffma2(a0[r][1], hv.x, V1[hp2].x); ffma2(a0[r][1], hv.y, V1[hp2].y);
                ffma2(a0[r][2], hv.x, v2.x); ffma2(a0[r][2], hv.y, v2.y);
                ffma2(a0[r][3], hv.x, v3.x); ffma2(a0[r][3], hv.y, v3.y);
            }
        }

        // ---- (4) A1: h1(t) from a1 ----
        #pragma unroll
        for (int r = 0; r < 4; ++r) {
            float gi  = redu(a1[r][0]);
            float gf  = redu(a1[r][1]);
            float gg_ = redu(a1[r][2]);
            float go  = redu(a1[r][3]);
            c1[r]  = sigma(gf) * c1[r] + sigma(gi) * tanha(gg_);
            h1v[r] = sigma(go) * tanha(c1[r]);
            ((float*)(hbase + r * 32))[32 + lane] = h1v[r];
        }
        __syncwarp();
    }

    #pragma unroll
    for (int r = 0; r < 4; ++r)
        g_comb[(size_t)(b0 + wg * 4 + r) * 1024 + f * 32 + lane] = h1v[r];
}

// ---------------------------------------------------------------------------
// Kernel 3: gaussian head. Block per b, 256 threads, float4 loads.
// ---------------------------------------------------------------------------
__global__ __launch_bounds__(256) void k_head(
    const float* __restrict__ mu_w, const float* __restrict__ mu_b,
    const float* __restrict__ lv_w, const float* __restrict__ lv_b,
    float* __restrict__ out)
{
    __shared__ float smu[8], slv[8];
    const int tid = threadIdx.x, b = blockIdx.x;

    float4 v  = ((const float4*)(g_comb + (size_t)b * 1024))[tid];
    float4 mw = ((const float4*)mu_w)[tid];
    float4 lw = ((const float4*)lv_w)[tid];
    float am = v.x * mw.x + v.y * mw.y + v.z * mw.z + v.w * mw.w;
    float al = v.x * lw.x + v.y * lw.y + v.z * lw.z + v.w * lw.w;

    #pragma unroll
    for (int s = 16; s > 0; s >>= 1) {
        am += __shfl_xor_sync(0xffffffffu, am, s);
        al += __shfl_xor_sync(0xffffffffu, al, s);
    }
    const int wg = tid >> 5, lane = tid & 31;
    if (lane == 0) { smu[wg] = am; slv[wg] = al; }
    __syncthreads();
    if (tid == 0) {
        float mu = mu_b[0], lv = lv_b[0];
        #pragma unroll
        for (int i = 0; i < 8; ++i) { mu += smu[i]; lv += slv[i]; }
        float sg = expf(0.5f * lv);
        out[b]       = mu - 1.96f * sg;
        out[128 + b] = mu;
        out[256 + b] = mu + 1.96f * sg;
        out[384 + b] = lv;
    }
}

// ---------------------------------------------------------------------------
extern "C" void kernel_launch(void* const* d_in, const int* in_sizes, int n_in,
                              void* d_out, int out_size)
{
    const float* x      = (const float*)d_in[0];
    const float* conv_w = (const float*)d_in[1];
    const float* conv_b = (const float*)d_in[2];
    const float* fc1_w  = (const float*)d_in[3];
    const float* fc1_b  = (const float*)d_in[4];
    const float* w_ih0  = (const float*)d_in[5];
    const float* w_ih1  = (const float*)d_in[6];
    const float* w_hh   = (const float*)d_in[7];
    const float* b_lstm = (const float*)d_in[8];
    const float* mu_w   = (const float*)d_in[9];
    const float* mu_b   = (const float*)d_in[10];
    const float* lv_w   = (const float*)d_in[11];
    const float* lv_b   = (const float*)d_in[12];
    float* out = (float*)d_out;

    const int SM_CF   = 53760 * (int)sizeof(float);                        // 215,040 B
    const int SM_LSTM = 9408 * (int)sizeof(ull);                           //  75,264 B

    cudaFuncSetAttribute(k_convfc, cudaFuncAttributeMaxDynamicSharedMemorySize, SM_CF);
    cudaFuncSetAttribute(k_lstm,   cudaFuncAttributeMaxDynamicSharedMemorySize, SM_LSTM);

    k_convfc<<<128, 512, SM_CF>>>(x, conv_w, conv_b, fc1_w, fc1_b);
    k_lstm<<<128, 256, SM_LSTM>>>(w_ih0, w_ih1, w_hh, b_lstm);
    k_head<<<128, 256>>>(mu_w, mu_b, lv_w, lv_b, out);
}